// round 12
// baseline (speedup 1.0000x reference)
#include <cuda_runtime.h>
#include <stdint.h>
#include <math.h>

#define NB 2
#define HIDC 10
#define HH 96
#define PIX (96*96)      // 9216
#define HP 47
#define SP (HP*HP)       // 2209
#define SPAD 2240        // padded spatial stride (64-multiple, 16B-aligned rows)
#define KSPLIT 4

// ---------------- scratch (device globals; no allocations) ----------------
__device__ float g_ppool[NB][256][SP];
__device__ float g_hupool[6][NB][HIDC][SP];
__device__ __align__(16) float g_qT[6][NB][18][SPAD];
__device__ __align__(16) float g_k[6][NB][18][SPAD];
__device__ __align__(16) float g_vp[6][NB][HIDC][SPAD];
__device__ float g_part[KSPLIT][6][NB][11][SP];
__device__ float g_ctxp[6][NB][HIDC][SP];
__device__ float g_Fdep[6][NB][HIDC][PIX];
__device__ float g_attsm[6][NB][4][PIX];
__device__ float g_dattu[NB][5][PIX];
__device__ float g_dattl[NB][3][PIX];
__device__ float g_msgs[6][NB][HIDC][PIX];

__constant__ int c_inc_cnt[6] = {1,3,2,1,2,1};
__constant__ int c_inc_u [6][3] = {{1,0,0},{0,2,4},{1,3,0},{2,0,0},{1,5,0},{4,0,0}};
__constant__ int c_inc_ch[6][3] = {{1,0,0},{1,1,1},{2,1,0},{2,0,0},{3,1,0},{2,0,0}};
__constant__ int c_nch[6]   = {2,4,3,2,3,2};
__constant__ int c_attoff[6]= {1253376,1290240,1363968,1419264,1456128,1511424};

__device__ __forceinline__ float coordf(int ch, int y, int x){
    const float inv = 1.0f/47.0f;
    switch(ch){
        case 0: return x*inv*2.0f-1.0f;
        case 1: return y*inv*2.0f-1.0f;
        case 2: return (x+1)*inv*2.0f-1.0f;
        case 3: return (y+1)*inv*2.0f-1.0f;
        case 4: return (2*x+1)*inv-1.0f;
        case 5: return (2*y+1)*inv-1.0f;
        default: return inv;
    }
}

__device__ __forceinline__ void cpa16(uint32_t dst, const void* src){
    asm volatile("cp.async.ca.shared.global [%0], [%1], 16;" :: "r"(dst), "l"(src));
}

// ---- packed f32x2 helpers (Blackwell sm_100+) ----
__device__ __forceinline__ uint64_t pk2(float lo, float hi){
    uint64_t r; asm("mov.b64 %0, {%1,%2};" : "=l"(r) : "f"(lo), "f"(hi)); return r;
}
__device__ __forceinline__ void upk2(uint64_t v, float& lo, float& hi){
    asm("mov.b64 {%0,%1}, %2;" : "=f"(lo), "=f"(hi) : "l"(v));
}
__device__ __forceinline__ uint64_t ffma2(uint64_t a, uint64_t b, uint64_t c){
    uint64_t d; asm("fma.rn.f32x2 %0, %1, %2, %3;" : "=l"(d) : "l"(a), "l"(b), "l"(c)); return d;
}
__device__ __forceinline__ uint64_t fmul2(uint64_t a, uint64_t b){
    uint64_t d; asm("mul.rn.f32x2 %0, %1, %2;" : "=l"(d) : "l"(a), "l"(b)); return d;
}
__device__ __forceinline__ uint64_t fadd2(uint64_t a, uint64_t b){
    uint64_t d; asm("add.rn.f32x2 %0, %1, %2;" : "=l"(d) : "l"(a), "l"(b)); return d;
}

// ---------------- K1: avgpool 3x3 stride 2 (xp and p_nodes) ----------------
__global__ void k_pool(const float* __restrict__ xp, const float* __restrict__ p_nodes){
    int idx = blockIdx.x*blockDim.x + threadIdx.x;
    const int T1 = NB*256*SP;
    const int T2 = 6*NB*HIDC*SP;
    if (idx < T1){
        int s=idx%SP; int c=(idx/SP)%256; int n=idx/(SP*256);
        int oy=s/HP, ox=s%HP;
        const float* src = xp + ((size_t)(n*256+c)*HH + 2*oy)*HH + 2*ox;
        float sum=0.f;
        #pragma unroll
        for(int dy=0;dy<3;dy++)
            #pragma unroll
            for(int dx=0;dx<3;dx++) sum += src[dy*HH+dx];
        g_ppool[n][c][s]=sum*(1.f/9.f);
    } else if (idx < T1+T2){
        int j=idx-T1;
        int s=j%SP; int c=(j/SP)%HIDC; int n=(j/(SP*HIDC))%NB; int i=j/(SP*HIDC*NB);
        int oy=s/HP, ox=s%HP;
        const float* src = p_nodes + ((size_t)((i*NB+n)*HIDC+c)*HH + 2*oy)*HH + 2*ox;
        float sum=0.f;
        #pragma unroll
        for(int dy=0;dy<3;dy++)
            #pragma unroll
            for(int dx=0;dx<3;dx++) sum += src[dy*HH+dx];
        g_hupool[i][n][c][s]=sum*(1.f/9.f);
    }
}

// ---------------- K2: q projection, transposed (padded) output -------------
__global__ void k_q(const float* __restrict__ Wq){
    int idx = blockIdx.x*blockDim.x + threadIdx.x;
    if (idx >= 6*NB*18*SPAD) return;
    int t=idx%SPAD; int o=(idx/SPAD)%18; int n=(idx/(SPAD*18))%NB; int i=idx/(SPAD*18*NB);
    if (t>=SP){ g_qT[i][n][o][t]=0.f; return; }
    const float* w = Wq + (i*18+o)*18;
    float acc=0.f;
    #pragma unroll
    for(int c=0;c<10;c++) acc += w[c]*g_hupool[i][n][c][t];
    int y=t/HP, x=t%HP;
    #pragma unroll
    for(int cc=0;cc<8;cc++) acc += w[10+cc]*coordf(cc,y,x);
    g_qT[i][n][o][t]=acc;
}

// ---------------- K3: fused k / v / vp, register-tiled --------------------
#define KV_CC 16
#define KV_NCHUNK 140   // 140*16 = 2240 = SPAD (covers pad region, zero-filled)
__global__ __launch_bounds__(128) void k_kv(
        const float* __restrict__ Wk, const float* __restrict__ Wv,
        const float* __restrict__ gv, const float* __restrict__ bv,
        const float* __restrict__ Wp){
    __shared__ float xs [256*20];
    __shared__ float xsT[16*260];
    __shared__ float vsm[128*20];
    int blk=blockIdx.x;
    int chunk=blk%KV_NCHUNK; int in_=blk/KV_NCHUNK; int n=in_%NB; int i=in_/NB;
    int s0=chunk*KV_CC;
    int tid=threadIdx.x;
    for(int idx=tid; idx<256*16; idx+=128){
        int c=idx>>4, col=idx&15; int s=s0+col;
        float v=(s<SP)? g_ppool[n][c][s] : 0.f;
        xs[c*20+col]=v; xsT[col*260+c]=v;
    }
    __syncthreads();

    int rg=tid>>2, cg=tid&3;
    int r0=rg*4, c0=cg*4;
    {
        const float* Wvi = Wv + i*128*256;
        float a[4][4];
        #pragma unroll
        for(int j=0;j<4;j++)
            #pragma unroll
            for(int l=0;l<4;l++) a[j][l]=0.f;
        for(int c=0;c<256;c+=4){
            float wv[4][4], xv[4][4];
            #pragma unroll
            for(int j=0;j<4;j++)
                *(float4*)wv[j] = *(const float4*)&Wvi[(r0+j)*256+c];
            #pragma unroll
            for(int cc=0;cc<4;cc++)
                *(float4*)xv[cc] = *(const float4*)&xs[(c+cc)*20+c0];
            #pragma unroll
            for(int cc=0;cc<4;cc++)
                #pragma unroll
                for(int j=0;j<4;j++)
                    #pragma unroll
                    for(int l=0;l<4;l++)
                        a[j][l] += wv[j][cc]*xv[cc][l];
        }
        #pragma unroll
        for(int j=0;j<4;j++){
            int r=r0+j;
            float g=gv[i*128+r], b=bv[i*128+r];
            float4 o4;
            o4.x=fmaxf(a[j][0]*g+b,0.f);
            o4.y=fmaxf(a[j][1]*g+b,0.f);
            o4.z=fmaxf(a[j][2]*g+b,0.f);
            o4.w=fmaxf(a[j][3]*g+b,0.f);
            *(float4*)&vsm[r*20+c0]=o4;
        }
    }
    {
        const float* Wki = Wk + i*18*264;
        for(int t=tid; t<18*16; t+=128){
            int o=t>>4, col=t&15;
            int s=s0+col;
            if (s>=SP){ g_k[i][n][o][s]=0.f; continue; }
            float acc=0.f;
            const float* w=Wki+o*264;
            const float* xc=&xsT[col*260];
            for(int c=0;c<256;c+=4){
                float4 w4=*(const float4*)&w[c];
                float4 x4=*(const float4*)&xc[c];
                acc += w4.x*x4.x + w4.y*x4.y + w4.z*x4.z + w4.w*x4.w;
            }
            int sy=s/HP, sx=s%HP;
            #pragma unroll
            for(int cc=0;cc<8;cc++) acc += w[256+cc]*coordf(cc,sy,sx);
            g_k[i][n][o][s]=acc;
        }
    }
    __syncthreads();
    {
        const float* Wpi = Wp + i*10*128;
        for(int t=tid; t<10*16; t+=128){
            int o=t>>4, col=t&15;
            int s=s0+col;
            if (s>=SP){ g_vp[i][n][o][s]=0.f; continue; }
            float acc=0.f;
            const float* w=Wpi+o*128;
            for(int r=0;r<128;r+=4){
                float4 w4=*(const float4*)&w[r];
                acc += w4.x*vsm[(r+0)*20+col] + w4.y*vsm[(r+1)*20+col]
                     + w4.z*vsm[(r+2)*20+col] + w4.w*vsm[(r+3)*20+col];
            }
            g_vp[i][n][o][s]=acc;
        }
    }
}

// ---------------- K4: attention, 3-stage cp.async ring, one sync/chunk -----
// grid: (35 q-tiles of 64, KSPLIT, 12), 128 threads
__global__ __launch_bounds__(128,5) void k_att(){
    __shared__ float qs [18*68];       // [c][q] pad 68
    __shared__ __align__(16) float ks [3][18*64];
    __shared__ __align__(16) float vps[3][10*64];
    int tt=blockIdx.x;
    int half=blockIdx.y;
    int in_=blockIdx.z; int n=in_%NB; int i=in_/NB;
    int t0=tt*64;
    int tid=threadIdx.x;
    int qg=tid>>3, kg=tid&7;

    uint32_t ksA[3], vpA[3];
    #pragma unroll
    for(int b=0;b<3;b++){
        ksA[b]=(uint32_t)__cvta_generic_to_shared(&ks[b][0]);
        vpA[b]=(uint32_t)__cvta_generic_to_shared(&vps[b][0]);
    }

    for(int idx=tid; idx<18*64; idx+=128){
        int c=idx>>6, r=idx&63;
        qs[c*68+r] = g_qT[i][n][c][t0+r];
    }
    float acc[4][11];
    #pragma unroll
    for(int j=0;j<4;j++)
        #pragma unroll
        for(int o=0;o<11;o++) acc[j][o]=0.f;

    int cA = half*9;
    int cB = min(35, cA+9);

    // prefetch chunks cA, cA+1
    #pragma unroll
    for(int pf=0; pf<2; pf++){
        if (cA+pf<cB){
            int s0=(cA+pf)*64;
            for(int j=tid; j<448; j+=128){
                if (j<288){ int o=j>>4, q2=j&15;
                    cpa16(ksA[pf]+(uint32_t)(o*64+q2*4)*4u, &g_k[i][n][o][s0+q2*4]);
                } else { int jj=j-288; int o=jj>>4, q2=jj&15;
                    cpa16(vpA[pf]+(uint32_t)(o*64+q2*4)*4u, &g_vp[i][n][o][s0+q2*4]);
                }
            }
            asm volatile("cp.async.commit_group;");
        }
    }

    for(int chunk=cA;chunk<cB;chunk++){
        int b=(chunk-cA)%3;
        if (chunk+1<cB) asm volatile("cp.async.wait_group 1;");
        else            asm volatile("cp.async.wait_group 0;");
        __syncthreads();   // also orders: compute(chunk-1) done before prefetch below
        if (chunk+2<cB){
            int nb=(chunk-cA+2)%3;
            int s0n=(chunk+2)*64;
            for(int j=tid; j<448; j+=128){
                if (j<288){ int o=j>>4, q2=j&15;
                    cpa16(ksA[nb]+(uint32_t)(o*64+q2*4)*4u, &g_k[i][n][o][s0n+q2*4]);
                } else { int jj=j-288; int o=jj>>4, q2=jj&15;
                    cpa16(vpA[nb]+(uint32_t)(o*64+q2*4)*4u, &g_vp[i][n][o][s0n+q2*4]);
                }
            }
            asm volatile("cp.async.commit_group;");
        }

        const float* ksb=&ks[b][0];
        const float* vpb=&vps[b][0];
        int s0=chunk*64;

        // ---- logits: e2[j][p] = packed pair (keys 2p, 2p+1) ----
        uint64_t e2[4][4];
        #pragma unroll
        for(int j=0;j<4;j++)
            #pragma unroll
            for(int p=0;p<4;p++) e2[j][p]=0ull;
        #pragma unroll 6
        for(int c=0;c<18;c++){
            float qv[4];
            *(float4*)qv = *(const float4*)&qs[c*68+qg*4];
            ulonglong2 k01 = *(const ulonglong2*)&ksb[c*64+kg*8];
            ulonglong2 k23 = *(const ulonglong2*)&ksb[c*64+kg*8+4];
            #pragma unroll
            for(int j=0;j<4;j++){
                uint64_t q2v = pk2(qv[j], qv[j]);
                e2[j][0] = ffma2(q2v, k01.x, e2[j][0]);
                e2[j][1] = ffma2(q2v, k01.y, e2[j][1]);
                e2[j][2] = ffma2(q2v, k23.x, e2[j][2]);
                e2[j][3] = ffma2(q2v, k23.y, e2[j][3]);
            }
        }
        // ---- exp ----
        if (s0+64 <= SP){
            #pragma unroll
            for(int j=0;j<4;j++)
                #pragma unroll
                for(int p=0;p<4;p++){
                    float lo,hi; upk2(e2[j][p],lo,hi);
                    e2[j][p]=pk2(__expf(lo),__expf(hi));
                }
        } else {
            int sb=s0+kg*8;
            #pragma unroll
            for(int j=0;j<4;j++)
                #pragma unroll
                for(int p=0;p<4;p++){
                    float lo,hi; upk2(e2[j][p],lo,hi);
                    lo = (sb+2*p  )<SP ? __expf(lo) : 0.f;
                    hi = (sb+2*p+1)<SP ? __expf(hi) : 0.f;
                    e2[j][p]=pk2(lo,hi);
                }
        }
        // ---- accumulate ----
        #pragma unroll
        for(int o=0;o<10;o++){
            ulonglong2 v01 = *(const ulonglong2*)&vpb[o*64+kg*8];
            ulonglong2 v23 = *(const ulonglong2*)&vpb[o*64+kg*8+4];
            #pragma unroll
            for(int j=0;j<4;j++){
                uint64_t t = fmul2(e2[j][3], v23.y);
                t = ffma2(e2[j][2], v23.x, t);
                t = ffma2(e2[j][1], v01.y, t);
                t = ffma2(e2[j][0], v01.x, t);
                float lo,hi; upk2(t,lo,hi);
                acc[j][o] += lo+hi;
            }
        }
        #pragma unroll
        for(int j=0;j<4;j++){
            uint64_t t = fadd2(fadd2(e2[j][0],e2[j][1]), fadd2(e2[j][2],e2[j][3]));
            float lo,hi; upk2(t,lo,hi);
            acc[j][10] += lo+hi;
        }
    }
    // reduce across the 8 key-lanes
    #pragma unroll
    for(int j=0;j<4;j++)
        #pragma unroll
        for(int o=0;o<11;o++){
            float v=acc[j][o];
            v += __shfl_xor_sync(0xffffffffu, v, 4, 8);
            v += __shfl_xor_sync(0xffffffffu, v, 2, 8);
            v += __shfl_xor_sync(0xffffffffu, v, 1, 8);
            acc[j][o]=v;
        }
    if (kg==0){
        #pragma unroll
        for(int j=0;j<4;j++){
            int t=t0+qg*4+j;
            if (t<SP){
                #pragma unroll
                for(int o=0;o<11;o++)
                    g_part[half][i][n][o][t]=acc[j][o];
            }
        }
    }
}

// ---------------- K4b: merge key-split partials, normalize, bn, relu ------
__global__ void k_att_fin(const float* __restrict__ gp, const float* __restrict__ bp){
    int idx=blockIdx.x*blockDim.x+threadIdx.x;
    if (idx >= 6*NB*SP) return;
    int t=idx%SP; int n=(idx/SP)%NB; int i=idx/(SP*NB);
    float a[11];
    #pragma unroll
    for(int o=0;o<11;o++){
        float v=0.f;
        #pragma unroll
        for(int h=0;h<KSPLIT;h++) v += g_part[h][i][n][o][t];
        a[o]=v;
    }
    float inv=1.f/a[10];
    #pragma unroll
    for(int o=0;o<10;o++){
        float val = a[o]*inv*gp[i*10+o]+bp[i*10+o];
        g_ctxp[i][n][o][t]=fmaxf(val,0.f);
    }
}

// ---------------- K5: bilinear upsample + att_list + softmax ---------------
__global__ void k_ups(const float* __restrict__ W_att, const float* __restrict__ b_att,
                      float* __restrict__ out){
    int idx=blockIdx.x*blockDim.x+threadIdx.x;
    if (idx >= 6*NB*PIX) return;
    int p=idx%PIX; int n=(idx/PIX)%NB; int i=idx/(PIX*NB);
    int y=p/HH, x=p%HH;
    const float sc=46.f/95.f;
    float sy=y*sc, sx=x*sc;
    int y0=(int)sy, x0=(int)sx;
    float fy=sy-(float)y0, fx=sx-(float)x0;
    int y1=min(y0+1,HP-1), x1=min(x0+1,HP-1);
    float w00=(1.f-fy)*(1.f-fx), w01=(1.f-fy)*fx, w10=fy*(1.f-fx), w11=fy*fx;
    int p00=y0*HP+x0, p01=y0*HP+x1, p10=y1*HP+x0, p11=y1*HP+x1;
    float f[10];
    #pragma unroll
    for(int c=0;c<10;c++){
        const float* cp=g_ctxp[i][n][c];
        float v=w00*cp[p00]+w01*cp[p01]+w10*cp[p10]+w11*cp[p11];
        f[c]=v; g_Fdep[i][n][c][p]=v;
    }
    int nch=c_nch[i];
    float a[4]; float m=-1e30f;
    for(int ch=0; ch<nch; ch++){
        const float* w=W_att+(i*4+ch)*10;
        float acc=b_att[i*4+ch];
        #pragma unroll
        for(int c=0;c<10;c++) acc += w[c]*f[c];
        a[ch]=acc; m=fmaxf(m,acc);
        out[c_attoff[i] + (n*nch+ch)*PIX + p]=acc;
    }
    float se=0.f;
    for(int ch=0; ch<nch; ch++){ a[ch]=__expf(a[ch]-m); se+=a[ch]; }
    float inv=1.f/se;
    for(int ch=0; ch<nch; ch++) g_attsm[i][n][ch][p]=a[ch]*inv;
}

// ---------------- K6: decomp maps + channel softmax ----------------
__global__ void k_maps(const float* __restrict__ h_nodes,
                       const float* __restrict__ W_du, const float* __restrict__ b_du,
                       const float* __restrict__ W_dl, const float* __restrict__ b_dl,
                       float* __restrict__ out){
    int idx=blockIdx.x*blockDim.x+threadIdx.x;
    if (idx >= NB*PIX) return;
    int p=idx%PIX; int n=idx/PIX;
    float hv[10];
    const float* h0 = h_nodes + (size_t)(0*NB+n)*HIDC*PIX;
    #pragma unroll
    for(int c=0;c<10;c++) hv[c]=h0[c*PIX+p];
    {
        float a[5]; float m=-1e30f;
        for(int k=0;k<5;k++){
            float acc=b_du[k];
            #pragma unroll
            for(int c=0;c<10;c++) acc += W_du[k*10+c]*hv[c];
            a[k]=acc; m=fmaxf(m,acc);
            out[1105920 + (n*5+k)*PIX + p]=acc;
        }
        float se=0.f;
        for(int k=0;k<5;k++){ a[k]=__expf(a[k]-m); se+=a[k]; }
        float inv=1.f/se;
        for(int k=0;k<5;k++) g_dattu[n][k][p]=a[k]*inv;
    }
    const float* h1 = h_nodes + (size_t)(1*NB+n)*HIDC*PIX;
    #pragma unroll
    for(int c=0;c<10;c++) hv[c]=h1[c*PIX+p];
    {
        float a[3]; float m=-1e30f;
        for(int k=0;k<3;k++){
            float acc=b_dl[k];
            #pragma unroll
            for(int c=0;c<10;c++) acc += W_dl[k*10+c]*hv[c];
            a[k]=acc; m=fmaxf(m,acc);
            out[1198080 + (n*3+k)*PIX + p]=acc;
        }
        float se=0.f;
        for(int k=0;k<3;k++){ a[k]=__expf(a[k]-m); se+=a[k]; }
        float inv=1.f/se;
        for(int k=0;k<3;k++) g_dattl[n][k][p]=a[k]*inv;
    }
}

// ---------------- K7: messages, smem-tiled 16x16 conv ---------------------
#define TS 16
#define THALO 18
#define THSZ (THALO*THALO)   // 324

// conv from smem tiles; out-of-bounds halo entries are zero (exact +0 to sums)
__device__ __forceinline__ void convS(const float* __restrict__ sfeat,
                                      const float* __restrict__ sgate,
                                      const float* __restrict__ spn,
                                      const float* __restrict__ W,
                                      int ty, int tx, float* acc){
    #pragma unroll
    for(int o=0;o<10;o++) acc[o]=0.f;
    #pragma unroll
    for(int ky=0;ky<3;ky++){
        #pragma unroll
        for(int kx=0;kx<3;kx++){
            int j=(ty+ky)*THALO+tx+kx; int tap=ky*3+kx;
            float gval=sgate[j];
            for(int c=0;c<10;c++){
                float a=sfeat[c*THSZ+j]*gval;
                float b=spn[c*THSZ+j];
                const float* wr = W + c*9 + tap;
                #pragma unroll
                for(int o=0;o<10;o++)
                    acc[o] += wr[o*180]*a + wr[o*180+90]*b;
            }
        }
    }
}

// load a 10-channel plane + gate plane with halo, zero-padded
__device__ __forceinline__ void load_tile10(const float* __restrict__ src,
                                            float* __restrict__ dst,
                                            int y0, int x0, int tid){
    for(int idx=tid; idx<10*THSZ; idx+=256){
        int c=idx/THSZ, j=idx%THSZ;
        int hy=y0-1+j/THALO, hx=x0-1+j%THALO;
        dst[idx] = (hy>=0 && hy<HH && hx>=0 && hx<HH)? src[c*PIX+hy*HH+hx] : 0.f;
    }
}
__device__ __forceinline__ void load_tile1(const float* __restrict__ src,
                                           float* __restrict__ dst,
                                           int y0, int x0, int tid){
    for(int idx=tid; idx<THSZ; idx+=256){
        int hy=y0-1+idx/THALO, hx=x0-1+idx%THALO;
        dst[idx] = (hy>=0 && hy<HH && hx>=0 && hx<HH)? src[hy*HH+hx] : 0.f;
    }
}

__global__ __launch_bounds__(256) void k_msgs(
        const float* __restrict__ h_nodes, const float* __restrict__ p_nodes,
        const float* __restrict__ W_decomp, const float* __restrict__ gdec,
        const float* __restrict__ bdec,
        const float* __restrict__ W_dep, const float* __restrict__ gdep,
        const float* __restrict__ bdep){
    __shared__ float wdec[1800], wdep[1800];
    __shared__ float spn [10*THSZ];
    __shared__ float sfeat[10*THSZ];
    __shared__ float sgate[THSZ];
    int tid=threadIdx.x;
    int tile=blockIdx.x;                 // 36 tiles (6x6)
    int vn=blockIdx.y; int v=vn/NB, n=vn%NB;
    int y0=(tile/6)*TS, x0=(tile%6)*TS;
    int ty=tid/TS, tx=tid%TS;
    int y=y0+ty, x=x0+tx;
    int p=y*HH+x;

    for(int j=tid;j<1800;j+=256){ wdec[j]=W_decomp[j]; wdep[j]=W_dep[j]; }
    const float* pn = p_nodes + (size_t)(v*NB+n)*HIDC*PIX;
    load_tile10(pn, spn, y0, x0, tid);

    float acc[10], msg[10];
    {
        int hsel = (v<4)?0:1;
        const float* feat = h_nodes + (size_t)(hsel*NB+n)*HIDC*PIX;
        const float* gate = (v<4)? &g_dattu[n][v+1][0] : &g_dattl[n][v-3][0];
        load_tile10(feat, sfeat, y0, x0, tid);
        load_tile1(gate, sgate, y0, x0, tid);
        __syncthreads();
        convS(sfeat, sgate, spn, wdec, ty, tx, acc);
        #pragma unroll
        for(int o=0;o<10;o++) msg[o]=fmaxf(gdec[o]*acc[o]+bdec[o], 0.f);
    }
    int cnt=c_inc_cnt[v];
    for(int e=0;e<cnt;e++){
        int u=c_inc_u[v][e], ch=c_inc_ch[v][e];
        __syncthreads();   // prior conv done before overwriting tiles
        load_tile10(&g_Fdep[u][n][0][0], sfeat, y0, x0, tid);
        load_tile1(&g_attsm[u][n][ch][0], sgate, y0, x0, tid);
        __syncthreads();
        convS(sfeat, sgate, spn, wdep, ty, tx, acc);
        #pragma unroll
        for(int o=0;o<10;o++) msg[o]+=fmaxf(gdep[o]*acc[o]+bdep[o], 0.f);
    }
    #pragma unroll
    for(int o=0;o<10;o++) g_msgs[v][n][o][p]=msg[o];
}

// ---------------- K8: ConvGRU (1x1) ----------------
__global__ void k_gru(const float* __restrict__ p_nodes,
                      const float* __restrict__ Wg, const float* __restrict__ bg,
                      const float* __restrict__ Wc, const float* __restrict__ bc,
                      float* __restrict__ out){
    __shared__ float swg[400], swc[200], sbg[20], sbc[10];
    int tid=threadIdx.x;
    int idx=blockIdx.x*256+tid;
    int p=idx%PIX; int n=(idx/PIX)%NB; int v=idx/(PIX*NB);
    for(int j=tid;j<400;j+=256) swg[j]=Wg[v*400+j];
    for(int j=tid;j<200;j+=256) swc[j]=Wc[v*200+j];
    if (tid<20) sbg[tid]=bg[v*20+tid];
    if (tid<10) sbc[tid]=bc[v*10+tid];
    __syncthreads();
    float m[10], h[10];
    #pragma unroll
    for(int c=0;c<10;c++){
        m[c]=g_msgs[v][n][c][p];
        h[c]=p_nodes[((size_t)(v*NB+n)*HIDC+c)*PIX+p];
    }
    float r[10], u[10];
    #pragma unroll
    for(int j=0;j<10;j++){
        float a=sbg[j];
        #pragma unroll
        for(int c=0;c<10;c++) a += swg[j*20+c]*m[c] + swg[j*20+10+c]*h[c];
        r[j]=1.f/(1.f+__expf(-a));
    }
    #pragma unroll
    for(int j=0;j<10;j++){
        float a=sbg[10+j];
        #pragma unroll
        for(int c=0;c<10;c++) a += swg[(10+j)*20+c]*m[c] + swg[(10+j)*20+10+c]*h[c];
        u[j]=1.f/(1.f+__expf(-a));
    }
    #pragma unroll
    for(int j=0;j<10;j++){
        float a=sbc[j];
        #pragma unroll
        for(int c=0;c<10;c++) a += swc[j*20+c]*m[c] + swc[j*20+10+c]*(r[c]*h[c]);
        float cand=tanhf(a);
        float o=(1.f-u[j])*h[j]+u[j]*cand;
        out[((size_t)(v*NB+n)*HIDC+j)*PIX+p]=o;
    }
}

// ---------------- host ----------------
extern "C" void kernel_launch(void* const* d_in, const int* in_sizes, int n_in,
                              void* d_out, int out_size){
    (void)in_sizes; (void)n_in; (void)out_size;
    const float* h_nodes  =(const float*)d_in[1];
    const float* p_nodes  =(const float*)d_in[2];
    const float* xp       =(const float*)d_in[3];
    const float* Wq       =(const float*)d_in[4];
    const float* Wk       =(const float*)d_in[5];
    const float* Wv       =(const float*)d_in[6];
    const float* gv       =(const float*)d_in[7];
    const float* bv       =(const float*)d_in[8];
    const float* Wp       =(const float*)d_in[9];
    const float* gp       =(const float*)d_in[10];
    const float* bp       =(const float*)d_in[11];
    const float* W_att    =(const float*)d_in[12];
    const float* b_att    =(const float*)d_in[13];
    const float* W_du     =(const float*)d_in[14];
    const float* b_du     =(const float*)d_in[15];
    const float* W_dl     =(const float*)d_in[16];
    const float* b_dl     =(const float*)d_in[17];
    const float* W_decomp =(const float*)d_in[18];
    const float* gdec     =(const float*)d_in[19];
    const float* bdec     =(const float*)d_in[20];
    const float* W_dep    =(const float*)d_in[21];
    const float* gdep     =(const float*)d_in[22];
    const float* bdep     =(const float*)d_in[23];
    const float* Wg       =(const float*)d_in[24];
    const float* bg       =(const float*)d_in[25];
    const float* Wc       =(const float*)d_in[26];
    const float* bc       =(const float*)d_in[27];
    float* out=(float*)d_out;

    {
        int total = NB*256*SP + 6*NB*HIDC*SP;
        k_pool<<<(total+255)/256, 256>>>(xp, p_nodes);
    }
    {
        int total = 6*NB*18*SPAD;
        k_q<<<(total+255)/256, 256>>>(Wq);
    }
    k_kv<<<6*NB*KV_NCHUNK, 128>>>(Wk, Wv, gv, bv, Wp);
    {
        dim3 grid(35, KSPLIT, 6*NB);
        k_att<<<grid, 128>>>();
    }
    k_att_fin<<<(6*NB*SP+255)/256, 256>>>(gp, bp);
    k_ups<<<(6*NB*PIX)/256, 256>>>(W_att, b_att, out);
    k_maps<<<(NB*PIX+255)/256, 256>>>(h_nodes, W_du, b_du, W_dl, b_dl, out);
    {
        dim3 grid(36, 6*NB);
        k_msgs<<<grid, 256>>>(h_nodes, p_nodes, W_decomp, gdec, bdec,
                              W_dep, gdep, bdep);
    }
    k_gru<<<(6*NB*PIX)/256, 256>>>(p_nodes, Wg, bg, Wc, bc, out);
}

// round 14
// speedup vs baseline: 1.0776x; 1.0776x over previous
#include <cuda_runtime.h>
#include <stdint.h>
#include <math.h>

#define NB 2
#define HIDC 10
#define HH 96
#define PIX (96*96)      // 9216
#define HP 47
#define SP (HP*HP)       // 2209
#define SPAD 2240        // padded spatial stride (64-multiple, 16B-aligned rows)
#define KSPLIT 4

// ---------------- scratch (device globals; no allocations) ----------------
__device__ float g_ppool[NB][256][SP];
__device__ float g_hupool[6][NB][HIDC][SP];
__device__ __align__(16) float g_qT[6][NB][18][SPAD];
__device__ __align__(16) float g_k[6][NB][18][SPAD];
__device__ __align__(16) float g_vp[6][NB][HIDC][SPAD];
__device__ float g_part[KSPLIT][6][NB][11][SP];
__device__ float g_ctxp[6][NB][HIDC][SP];
__device__ float g_Fdep[6][NB][HIDC][PIX];
__device__ float g_attsm[6][NB][4][PIX];
__device__ float g_dattu[NB][5][PIX];
__device__ float g_dattl[NB][3][PIX];
__device__ float g_msgs[6][NB][HIDC][PIX];

__constant__ int c_inc_cnt[6] = {1,3,2,1,2,1};
__constant__ int c_inc_u [6][3] = {{1,0,0},{0,2,4},{1,3,0},{2,0,0},{1,5,0},{4,0,0}};
__constant__ int c_inc_ch[6][3] = {{1,0,0},{1,1,1},{2,1,0},{2,0,0},{3,1,0},{2,0,0}};
__constant__ int c_nch[6]   = {2,4,3,2,3,2};
__constant__ int c_attoff[6]= {1253376,1290240,1363968,1419264,1456128,1511424};

__device__ __forceinline__ float coordf(int ch, int y, int x){
    const float inv = 1.0f/47.0f;
    switch(ch){
        case 0: return x*inv*2.0f-1.0f;
        case 1: return y*inv*2.0f-1.0f;
        case 2: return (x+1)*inv*2.0f-1.0f;
        case 3: return (y+1)*inv*2.0f-1.0f;
        case 4: return (2*x+1)*inv-1.0f;
        case 5: return (2*y+1)*inv-1.0f;
        default: return inv;
    }
}

__device__ __forceinline__ void cpa16(uint32_t dst, const void* src){
    asm volatile("cp.async.ca.shared.global [%0], [%1], 16;" :: "r"(dst), "l"(src));
}

// ---- packed f32x2 helpers (Blackwell sm_100+) ----
__device__ __forceinline__ uint64_t pk2(float lo, float hi){
    uint64_t r; asm("mov.b64 %0, {%1,%2};" : "=l"(r) : "f"(lo), "f"(hi)); return r;
}
__device__ __forceinline__ void upk2(uint64_t v, float& lo, float& hi){
    asm("mov.b64 {%0,%1}, %2;" : "=f"(lo), "=f"(hi) : "l"(v));
}
__device__ __forceinline__ uint64_t ffma2(uint64_t a, uint64_t b, uint64_t c){
    uint64_t d; asm("fma.rn.f32x2 %0, %1, %2, %3;" : "=l"(d) : "l"(a), "l"(b), "l"(c)); return d;
}
__device__ __forceinline__ uint64_t fmul2(uint64_t a, uint64_t b){
    uint64_t d; asm("mul.rn.f32x2 %0, %1, %2;" : "=l"(d) : "l"(a), "l"(b)); return d;
}
__device__ __forceinline__ uint64_t fadd2(uint64_t a, uint64_t b){
    uint64_t d; asm("add.rn.f32x2 %0, %1, %2;" : "=l"(d) : "l"(a), "l"(b)); return d;
}

// ---------------- K1: avgpool 3x3 stride 2 (xp and p_nodes) ----------------
__global__ void k_pool(const float* __restrict__ xp, const float* __restrict__ p_nodes){
    int idx = blockIdx.x*blockDim.x + threadIdx.x;
    const int T1 = NB*256*SP;
    const int T2 = 6*NB*HIDC*SP;
    if (idx < T1){
        int s=idx%SP; int c=(idx/SP)%256; int n=idx/(SP*256);
        int oy=s/HP, ox=s%HP;
        const float* src = xp + ((size_t)(n*256+c)*HH + 2*oy)*HH + 2*ox;
        float sum=0.f;
        #pragma unroll
        for(int dy=0;dy<3;dy++)
            #pragma unroll
            for(int dx=0;dx<3;dx++) sum += src[dy*HH+dx];
        g_ppool[n][c][s]=sum*(1.f/9.f);
    } else if (idx < T1+T2){
        int j=idx-T1;
        int s=j%SP; int c=(j/SP)%HIDC; int n=(j/(SP*HIDC))%NB; int i=j/(SP*HIDC*NB);
        int oy=s/HP, ox=s%HP;
        const float* src = p_nodes + ((size_t)((i*NB+n)*HIDC+c)*HH + 2*oy)*HH + 2*ox;
        float sum=0.f;
        #pragma unroll
        for(int dy=0;dy<3;dy++)
            #pragma unroll
            for(int dx=0;dx<3;dx++) sum += src[dy*HH+dx];
        g_hupool[i][n][c][s]=sum*(1.f/9.f);
    }
}

// ---------------- K2: q projection, transposed (padded) output -------------
__global__ void k_q(const float* __restrict__ Wq){
    int idx = blockIdx.x*blockDim.x + threadIdx.x;
    if (idx >= 6*NB*18*SPAD) return;
    int t=idx%SPAD; int o=(idx/SPAD)%18; int n=(idx/(SPAD*18))%NB; int i=idx/(SPAD*18*NB);
    if (t>=SP){ g_qT[i][n][o][t]=0.f; return; }
    const float* w = Wq + (i*18+o)*18;
    float acc=0.f;
    #pragma unroll
    for(int c=0;c<10;c++) acc += w[c]*g_hupool[i][n][c][t];
    int y=t/HP, x=t%HP;
    #pragma unroll
    for(int cc=0;cc<8;cc++) acc += w[10+cc]*coordf(cc,y,x);
    g_qT[i][n][o][t]=acc;
}

// ---------------- K3: fused k / v / vp, 32-col tile, 256 threads -----------
#define KV_CC 32
#define KV_NCHUNK 70    // 70*32 = 2240 = SPAD (covers pad region, zero-filled)
__global__ __launch_bounds__(256) void k_kv(
        const float* __restrict__ Wk, const float* __restrict__ Wv,
        const float* __restrict__ gv, const float* __restrict__ bv,
        const float* __restrict__ Wp){
    __shared__ float xs [256*32];   // [c][col], 32 KB
    __shared__ float vsm[128*32];   // [r][col], 16 KB
    int blk=blockIdx.x;
    int chunk=blk%KV_NCHUNK; int in_=blk/KV_NCHUNK; int n=in_%NB; int i=in_/NB;
    int s0=chunk*KV_CC;
    int tid=threadIdx.x;
    for(int idx=tid; idx<256*32; idx+=256){
        int c=idx>>5, col=idx&31; int s=s0+col;
        xs[idx] = (s<SP)? g_ppool[n][c][s] : 0.f;
    }
    __syncthreads();

    int rg=tid>>3, cg=tid&7;      // rg 0..31 (4 rows each), cg 0..7 (4 cols each)
    int r0=rg*4, c0=cg*4;
    // ---- stage 1: v = relu(bn(Wv@x)), 4x4 register tile ----
    {
        const float* Wvi = Wv + i*128*256;
        float a[4][4];
        #pragma unroll
        for(int j=0;j<4;j++)
            #pragma unroll
            for(int l=0;l<4;l++) a[j][l]=0.f;
        for(int c=0;c<256;c+=4){
            float wv[4][4], xv[4][4];
            #pragma unroll
            for(int j=0;j<4;j++)
                *(float4*)wv[j] = *(const float4*)&Wvi[(r0+j)*256+c];
            #pragma unroll
            for(int cc=0;cc<4;cc++)
                *(float4*)xv[cc] = *(const float4*)&xs[(c+cc)*32+c0];
            #pragma unroll
            for(int cc=0;cc<4;cc++)
                #pragma unroll
                for(int j=0;j<4;j++)
                    #pragma unroll
                    for(int l=0;l<4;l++)
                        a[j][l] += wv[j][cc]*xv[cc][l];
        }
        #pragma unroll
        for(int j=0;j<4;j++){
            int r=r0+j;
            float g=gv[i*128+r], b=bv[i*128+r];
            float4 o4;
            o4.x=fmaxf(a[j][0]*g+b,0.f);
            o4.y=fmaxf(a[j][1]*g+b,0.f);
            o4.z=fmaxf(a[j][2]*g+b,0.f);
            o4.w=fmaxf(a[j][3]*g+b,0.f);
            *(float4*)&vsm[r*32+c0]=o4;
        }
    }
    // ---- stage 2: k projection (18 rows x 32 cols) ----
    {
        const float* Wki = Wk + i*18*264;
        for(int t=tid; t<18*32; t+=256){
            int o=t>>5, col=t&31;
            int s=s0+col;
            if (s>=SP){ g_k[i][n][o][s]=0.f; continue; }
            float acc=0.f;
            const float* w=Wki+o*264;
            for(int c=0;c<256;c+=4){
                float4 w4=*(const float4*)&w[c];
                acc += w4.x*xs[(c+0)*32+col] + w4.y*xs[(c+1)*32+col]
                     + w4.z*xs[(c+2)*32+col] + w4.w*xs[(c+3)*32+col];
            }
            int sy=s/HP, sx=s%HP;
            #pragma unroll
            for(int cc=0;cc<8;cc++) acc += w[256+cc]*coordf(cc,sy,sx);
            g_k[i][n][o][s]=acc;
        }
    }
    __syncthreads();
    // ---- stage 3: vp = Wp @ vsm (10 rows x 32 cols) ----
    {
        const float* Wpi = Wp + i*10*128;
        for(int t=tid; t<10*32; t+=256){
            int o=t>>5, col=t&31;
            int s=s0+col;
            if (s>=SP){ g_vp[i][n][o][s]=0.f; continue; }
            float acc=0.f;
            const float* w=Wpi+o*128;
            for(int r=0;r<128;r+=4){
                float4 w4=*(const float4*)&w[r];
                acc += w4.x*vsm[(r+0)*32+col] + w4.y*vsm[(r+1)*32+col]
                     + w4.z*vsm[(r+2)*32+col] + w4.w*vsm[(r+3)*32+col];
            }
            g_vp[i][n][o][s]=acc;
        }
    }
}

// ---------------- K4: attention, 3-stage cp.async ring, one sync/chunk -----
// grid: (35 q-tiles of 64, KSPLIT, 12), 128 threads
__global__ __launch_bounds__(128,5) void k_att(){
    __shared__ float qs [18*68];       // [c][q] pad 68
    __shared__ __align__(16) float ks [3][18*64];
    __shared__ __align__(16) float vps[3][10*64];
    int tt=blockIdx.x;
    int half=blockIdx.y;
    int in_=blockIdx.z; int n=in_%NB; int i=in_/NB;
    int t0=tt*64;
    int tid=threadIdx.x;
    int qg=tid>>3, kg=tid&7;

    uint32_t ksA[3], vpA[3];
    #pragma unroll
    for(int b=0;b<3;b++){
        ksA[b]=(uint32_t)__cvta_generic_to_shared(&ks[b][0]);
        vpA[b]=(uint32_t)__cvta_generic_to_shared(&vps[b][0]);
    }

    for(int idx=tid; idx<18*64; idx+=128){
        int c=idx>>6, r=idx&63;
        qs[c*68+r] = g_qT[i][n][c][t0+r];
    }
    float acc[4][11];
    #pragma unroll
    for(int j=0;j<4;j++)
        #pragma unroll
        for(int o=0;o<11;o++) acc[j][o]=0.f;

    int cA = half*9;
    int cB = min(35, cA+9);

    // prefetch chunks cA, cA+1
    #pragma unroll
    for(int pf=0; pf<2; pf++){
        if (cA+pf<cB){
            int s0=(cA+pf)*64;
            for(int j=tid; j<448; j+=128){
                if (j<288){ int o=j>>4, q2=j&15;
                    cpa16(ksA[pf]+(uint32_t)(o*64+q2*4)*4u, &g_k[i][n][o][s0+q2*4]);
                } else { int jj=j-288; int o=jj>>4, q2=jj&15;
                    cpa16(vpA[pf]+(uint32_t)(o*64+q2*4)*4u, &g_vp[i][n][o][s0+q2*4]);
                }
            }
            asm volatile("cp.async.commit_group;");
        }
    }

    for(int chunk=cA;chunk<cB;chunk++){
        int b=(chunk-cA)%3;
        if (chunk+1<cB) asm volatile("cp.async.wait_group 1;");
        else            asm volatile("cp.async.wait_group 0;");
        __syncthreads();   // also orders: compute(chunk-1) done before prefetch below
        if (chunk+2<cB){
            int nb=(chunk-cA+2)%3;
            int s0n=(chunk+2)*64;
            for(int j=tid; j<448; j+=128){
                if (j<288){ int o=j>>4, q2=j&15;
                    cpa16(ksA[nb]+(uint32_t)(o*64+q2*4)*4u, &g_k[i][n][o][s0n+q2*4]);
                } else { int jj=j-288; int o=jj>>4, q2=jj&15;
                    cpa16(vpA[nb]+(uint32_t)(o*64+q2*4)*4u, &g_vp[i][n][o][s0n+q2*4]);
                }
            }
            asm volatile("cp.async.commit_group;");
        }

        const float* ksb=&ks[b][0];
        const float* vpb=&vps[b][0];
        int s0=chunk*64;

        // ---- logits: e2[j][p] = packed pair (keys 2p, 2p+1) ----
        uint64_t e2[4][4];
        #pragma unroll
        for(int j=0;j<4;j++)
            #pragma unroll
            for(int p=0;p<4;p++) e2[j][p]=0ull;
        #pragma unroll 6
        for(int c=0;c<18;c++){
            float qv[4];
            *(float4*)qv = *(const float4*)&qs[c*68+qg*4];
            ulonglong2 k01 = *(const ulonglong2*)&ksb[c*64+kg*8];
            ulonglong2 k23 = *(const ulonglong2*)&ksb[c*64+kg*8+4];
            #pragma unroll
            for(int j=0;j<4;j++){
                uint64_t q2v = pk2(qv[j], qv[j]);
                e2[j][0] = ffma2(q2v, k01.x, e2[j][0]);
                e2[j][1] = ffma2(q2v, k01.y, e2[j][1]);
                e2[j][2] = ffma2(q2v, k23.x, e2[j][2]);
                e2[j][3] = ffma2(q2v, k23.y, e2[j][3]);
            }
        }
        // ---- exp ----
        if (s0+64 <= SP){
            #pragma unroll
            for(int j=0;j<4;j++)
                #pragma unroll
                for(int p=0;p<4;p++){
                    float lo,hi; upk2(e2[j][p],lo,hi);
                    e2[j][p]=pk2(__expf(lo),__expf(hi));
                }
        } else {
            int sb=s0+kg*8;
            #pragma unroll
            for(int j=0;j<4;j++)
                #pragma unroll
                for(int p=0;p<4;p++){
                    float lo,hi; upk2(e2[j][p],lo,hi);
                    lo = (sb+2*p  )<SP ? __expf(lo) : 0.f;
                    hi = (sb+2*p+1)<SP ? __expf(hi) : 0.f;
                    e2[j][p]=pk2(lo,hi);
                }
        }
        // ---- accumulate ----
        #pragma unroll
        for(int o=0;o<10;o++){
            ulonglong2 v01 = *(const ulonglong2*)&vpb[o*64+kg*8];
            ulonglong2 v23 = *(const ulonglong2*)&vpb[o*64+kg*8+4];
            #pragma unroll
            for(int j=0;j<4;j++){
                uint64_t t = fmul2(e2[j][3], v23.y);
                t = ffma2(e2[j][2], v23.x, t);
                t = ffma2(e2[j][1], v01.y, t);
                t = ffma2(e2[j][0], v01.x, t);
                float lo,hi; upk2(t,lo,hi);
                acc[j][o] += lo+hi;
            }
        }
        #pragma unroll
        for(int j=0;j<4;j++){
            uint64_t t = fadd2(fadd2(e2[j][0],e2[j][1]), fadd2(e2[j][2],e2[j][3]));
            float lo,hi; upk2(t,lo,hi);
            acc[j][10] += lo+hi;
        }
    }
    // reduce across the 8 key-lanes
    #pragma unroll
    for(int j=0;j<4;j++)
        #pragma unroll
        for(int o=0;o<11;o++){
            float v=acc[j][o];
            v += __shfl_xor_sync(0xffffffffu, v, 4, 8);
            v += __shfl_xor_sync(0xffffffffu, v, 2, 8);
            v += __shfl_xor_sync(0xffffffffu, v, 1, 8);
            acc[j][o]=v;
        }
    if (kg==0){
        #pragma unroll
        for(int j=0;j<4;j++){
            int t=t0+qg*4+j;
            if (t<SP){
                #pragma unroll
                for(int o=0;o<11;o++)
                    g_part[half][i][n][o][t]=acc[j][o];
            }
        }
    }
}

// ---------------- K4b: merge key-split partials, normalize, bn, relu ------
__global__ void k_att_fin(const float* __restrict__ gp, const float* __restrict__ bp){
    int idx=blockIdx.x*blockDim.x+threadIdx.x;
    if (idx >= 6*NB*SP) return;
    int t=idx%SP; int n=(idx/SP)%NB; int i=idx/(SP*NB);
    float a[11];
    #pragma unroll
    for(int o=0;o<11;o++){
        float v=0.f;
        #pragma unroll
        for(int h=0;h<KSPLIT;h++) v += g_part[h][i][n][o][t];
        a[o]=v;
    }
    float inv=1.f/a[10];
    #pragma unroll
    for(int o=0;o<10;o++){
        float val = a[o]*inv*gp[i*10+o]+bp[i*10+o];
        g_ctxp[i][n][o][t]=fmaxf(val,0.f);
    }
}

// ---------------- K5: bilinear upsample + att_list + softmax ---------------
__global__ void k_ups(const float* __restrict__ W_att, const float* __restrict__ b_att,
                      float* __restrict__ out){
    int idx=blockIdx.x*blockDim.x+threadIdx.x;
    if (idx >= 6*NB*PIX) return;
    int p=idx%PIX; int n=(idx/PIX)%NB; int i=idx/(PIX*NB);
    int y=p/HH, x=p%HH;
    const float sc=46.f/95.f;
    float sy=y*sc, sx=x*sc;
    int y0=(int)sy, x0=(int)sx;
    float fy=sy-(float)y0, fx=sx-(float)x0;
    int y1=min(y0+1,HP-1), x1=min(x0+1,HP-1);
    float w00=(1.f-fy)*(1.f-fx), w01=(1.f-fy)*fx, w10=fy*(1.f-fx), w11=fy*fx;
    int p00=y0*HP+x0, p01=y0*HP+x1, p10=y1*HP+x0, p11=y1*HP+x1;
    float f[10];
    #pragma unroll
    for(int c=0;c<10;c++){
        const float* cp=g_ctxp[i][n][c];
        float v=w00*cp[p00]+w01*cp[p01]+w10*cp[p10]+w11*cp[p11];
        f[c]=v; g_Fdep[i][n][c][p]=v;
    }
    int nch=c_nch[i];
    float a[4]; float m=-1e30f;
    for(int ch=0; ch<nch; ch++){
        const float* w=W_att+(i*4+ch)*10;
        float acc=b_att[i*4+ch];
        #pragma unroll
        for(int c=0;c<10;c++) acc += w[c]*f[c];
        a[ch]=acc; m=fmaxf(m,acc);
        out[c_attoff[i] + (n*nch+ch)*PIX + p]=acc;
    }
    float se=0.f;
    for(int ch=0; ch<nch; ch++){ a[ch]=__expf(a[ch]-m); se+=a[ch]; }
    float inv=1.f/se;
    for(int ch=0; ch<nch; ch++) g_attsm[i][n][ch][p]=a[ch]*inv;
}

// ---------------- K6: decomp maps + channel softmax ----------------
__global__ void k_maps(const float* __restrict__ h_nodes,
                       const float* __restrict__ W_du, const float* __restrict__ b_du,
                       const float* __restrict__ W_dl, const float* __restrict__ b_dl,
                       float* __restrict__ out){
    int idx=blockIdx.x*blockDim.x+threadIdx.x;
    if (idx >= NB*PIX) return;
    int p=idx%PIX; int n=idx/PIX;
    float hv[10];
    const float* h0 = h_nodes + (size_t)(0*NB+n)*HIDC*PIX;
    #pragma unroll
    for(int c=0;c<10;c++) hv[c]=h0[c*PIX+p];
    {
        float a[5]; float m=-1e30f;
        for(int k=0;k<5;k++){
            float acc=b_du[k];
            #pragma unroll
            for(int c=0;c<10;c++) acc += W_du[k*10+c]*hv[c];
            a[k]=acc; m=fmaxf(m,acc);
            out[1105920 + (n*5+k)*PIX + p]=acc;
        }
        float se=0.f;
        for(int k=0;k<5;k++){ a[k]=__expf(a[k]-m); se+=a[k]; }
        float inv=1.f/se;
        for(int k=0;k<5;k++) g_dattu[n][k][p]=a[k]*inv;
    }
    const float* h1 = h_nodes + (size_t)(1*NB+n)*HIDC*PIX;
    #pragma unroll
    for(int c=0;c<10;c++) hv[c]=h1[c*PIX+p];
    {
        float a[3]; float m=-1e30f;
        for(int k=0;k<3;k++){
            float acc=b_dl[k];
            #pragma unroll
            for(int c=0;c<10;c++) acc += W_dl[k*10+c]*hv[c];
            a[k]=acc; m=fmaxf(m,acc);
            out[1198080 + (n*3+k)*PIX + p]=acc;
        }
        float se=0.f;
        for(int k=0;k<3;k++){ a[k]=__expf(a[k]-m); se+=a[k]; }
        float inv=1.f/se;
        for(int k=0;k<3;k++) g_dattl[n][k][p]=a[k]*inv;
    }
}

// 3x3 conv, 20 in-ch (10 gated feat + 10 plain), all 10 out-ch per thread
__device__ __forceinline__ void conv20(const float* __restrict__ feat, const float* __restrict__ gate,
                                       const float* __restrict__ pn, const float* __restrict__ W,
                                       int y, int x, float* acc){
    #pragma unroll
    for(int o=0;o<10;o++) acc[o]=0.f;
    #pragma unroll
    for(int ky=0;ky<3;ky++){
        int yy=y+ky-1; if (yy<0||yy>=HH) continue;
        #pragma unroll
        for(int kx=0;kx<3;kx++){
            int xx=x+kx-1; if (xx<0||xx>=HH) continue;
            int pp=yy*HH+xx; int tap=ky*3+kx;
            float gval=gate[pp];
            for(int c=0;c<10;c++){
                float a=feat[c*PIX+pp]*gval;
                float b=pn[c*PIX+pp];
                const float* wr = W + c*9 + tap;
                #pragma unroll
                for(int o=0;o<10;o++)
                    acc[o] += wr[o*180]*a + wr[o*180+90]*b;
            }
        }
    }
}

// ---------------- K7: messages = decomp conv + sum of incoming dep convs ----
__global__ void k_msgs(const float* __restrict__ h_nodes, const float* __restrict__ p_nodes,
                       const float* __restrict__ W_decomp, const float* __restrict__ gdec,
                       const float* __restrict__ bdec,
                       const float* __restrict__ W_dep, const float* __restrict__ gdep,
                       const float* __restrict__ bdep){
    __shared__ float wdec[1800], wdep[1800];
    int tid=threadIdx.x;
    for(int j=tid;j<1800;j+=256){ wdec[j]=W_decomp[j]; wdep[j]=W_dep[j]; }
    __syncthreads();
    int idx=blockIdx.x*256+tid;
    if (idx >= 6*NB*PIX) return;
    int p=idx%PIX; int n=(idx/PIX)%NB; int v=idx/(PIX*NB);
    int y=p/HH, x=p%HH;
    const float* pn = p_nodes + (size_t)(v*NB+n)*HIDC*PIX;
    float acc[10], msg[10];
    {
        int hsel = (v<4)?0:1;
        const float* feat = h_nodes + (size_t)(hsel*NB+n)*HIDC*PIX;
        const float* gate = (v<4)? &g_dattu[n][v+1][0] : &g_dattl[n][v-3][0];
        conv20(feat, gate, pn, wdec, y, x, acc);
        #pragma unroll
        for(int o=0;o<10;o++) msg[o]=fmaxf(gdec[o]*acc[o]+bdec[o], 0.f);
    }
    int cnt=c_inc_cnt[v];
    for(int e=0;e<cnt;e++){
        int u=c_inc_u[v][e], ch=c_inc_ch[v][e];
        conv20(&g_Fdep[u][n][0][0], &g_attsm[u][n][ch][0], pn, wdep, y, x, acc);
        #pragma unroll
        for(int o=0;o<10;o++) msg[o]+=fmaxf(gdep[o]*acc[o]+bdep[o], 0.f);
    }
    #pragma unroll
    for(int o=0;o<10;o++) g_msgs[v][n][o][p]=msg[o];
}

// ---------------- K8: ConvGRU (1x1) ----------------
__global__ void k_gru(const float* __restrict__ p_nodes,
                      const float* __restrict__ Wg, const float* __restrict__ bg,
                      const float* __restrict__ Wc, const float* __restrict__ bc,
                      float* __restrict__ out){
    __shared__ float swg[400], swc[200], sbg[20], sbc[10];
    int tid=threadIdx.x;
    int idx=blockIdx.x*256+tid;
    int p=idx%PIX; int n=(idx/PIX)%NB; int v=idx/(PIX*NB);
    for(int j=tid;j<400;j+=256) swg[j]=Wg[v*400+j];
    for(int j=tid;j<200;j+=256) swc[j]=Wc[v*200+j];
    if (tid<20) sbg[tid]=bg[v*20+tid];
    if (tid<10) sbc[tid]=bc[v*10+tid];
    __syncthreads();
    float m[10], h[10];
    #pragma unroll
    for(int c=0;c<10;c++){
        m[c]=g_msgs[v][n][c][p];
        h[c]=p_nodes[((size_t)(v*NB+n)*HIDC+c)*PIX+p];
    }
    float r[10], u[10];
    #pragma unroll
    for(int j=0;j<10;j++){
        float a=sbg[j];
        #pragma unroll
        for(int c=0;c<10;c++) a += swg[j*20+c]*m[c] + swg[j*20+10+c]*h[c];
        r[j]=1.f/(1.f+__expf(-a));
    }
    #pragma unroll
    for(int j=0;j<10;j++){
        float a=sbg[10+j];
        #pragma unroll
        for(int c=0;c<10;c++) a += swg[(10+j)*20+c]*m[c] + swg[(10+j)*20+10+c]*h[c];
        u[j]=1.f/(1.f+__expf(-a));
    }
    #pragma unroll
    for(int j=0;j<10;j++){
        float a=sbc[j];
        #pragma unroll
        for(int c=0;c<10;c++) a += swc[j*20+c]*m[c] + swc[j*20+10+c]*(r[c]*h[c]);
        float cand=tanhf(a);
        float o=(1.f-u[j])*h[j]+u[j]*cand;
        out[((size_t)(v*NB+n)*HIDC+j)*PIX+p]=o;
    }
}

// ---------------- host ----------------
extern "C" void kernel_launch(void* const* d_in, const int* in_sizes, int n_in,
                              void* d_out, int out_size){
    (void)in_sizes; (void)n_in; (void)out_size;
    const float* h_nodes  =(const float*)d_in[1];
    const float* p_nodes  =(const float*)d_in[2];
    const float* xp       =(const float*)d_in[3];
    const float* Wq       =(const float*)d_in[4];
    const float* Wk       =(const float*)d_in[5];
    const float* Wv       =(const float*)d_in[6];
    const float* gv       =(const float*)d_in[7];
    const float* bv       =(const float*)d_in[8];
    const float* Wp       =(const float*)d_in[9];
    const float* gp       =(const float*)d_in[10];
    const float* bp       =(const float*)d_in[11];
    const float* W_att    =(const float*)d_in[12];
    const float* b_att    =(const float*)d_in[13];
    const float* W_du     =(const float*)d_in[14];
    const float* b_du     =(const float*)d_in[15];
    const float* W_dl     =(const float*)d_in[16];
    const float* b_dl     =(const float*)d_in[17];
    const float* W_decomp =(const float*)d_in[18];
    const float* gdec     =(const float*)d_in[19];
    const float* bdec     =(const float*)d_in[20];
    const float* W_dep    =(const float*)d_in[21];
    const float* gdep     =(const float*)d_in[22];
    const float* bdep     =(const float*)d_in[23];
    const float* Wg       =(const float*)d_in[24];
    const float* bg       =(const float*)d_in[25];
    const float* Wc       =(const float*)d_in[26];
    const float* bc       =(const float*)d_in[27];
    float* out=(float*)d_out;

    {
        int total = NB*256*SP + 6*NB*HIDC*SP;
        k_pool<<<(total+255)/256, 256>>>(xp, p_nodes);
    }
    {
        int total = 6*NB*18*SPAD;
        k_q<<<(total+255)/256, 256>>>(Wq);
    }
    k_kv<<<6*NB*KV_NCHUNK, 256>>>(Wk, Wv, gv, bv, Wp);
    {
        dim3 grid(35, KSPLIT, 6*NB);
        k_att<<<grid, 128>>>();
    }
    k_att_fin<<<(6*NB*SP+255)/256, 256>>>(gp, bp);
    k_ups<<<(6*NB*PIX)/256, 256>>>(W_att, b_att, out);
    k_maps<<<(NB*PIX+255)/256, 256>>>(h_nodes, W_du, b_du, W_dl, b_dl, out);
    k_msgs<<<(6*NB*PIX)/256, 256>>>(h_nodes, p_nodes, W_decomp, gdec, bdec,
                                    W_dep, gdep, bdep);
    k_gru<<<(6*NB*PIX)/256, 256>>>(p_nodes, Wg, bg, Wc, bc, out);
}

// round 15
// speedup vs baseline: 1.1210x; 1.0402x over previous
#include <cuda_runtime.h>
#include <stdint.h>
#include <math.h>

#define NB 2
#define HIDC 10
#define HH 96
#define PIX (96*96)      // 9216
#define HP 47
#define SP (HP*HP)       // 2209
#define SPAD 2240        // padded spatial stride (64-multiple, 16B-aligned rows)
#define KSPLIT 7

// ---------------- scratch (device globals; no allocations) ----------------
__device__ float g_ppool[NB][256][SP];
__device__ float g_hupool[6][NB][HIDC][SP];
__device__ __align__(16) float g_qT[6][NB][18][SPAD];
__device__ __align__(16) float g_k[6][NB][18][SPAD];
__device__ __align__(16) float g_vp[6][NB][HIDC][SPAD];
__device__ float g_part[KSPLIT][6][NB][11][SP];
__device__ float g_ctxp[6][NB][HIDC][SP];
__device__ float g_Fdep[6][NB][HIDC][PIX];
__device__ float g_attsm[6][NB][4][PIX];
__device__ float g_dattu[NB][5][PIX];
__device__ float g_dattl[NB][3][PIX];
__device__ float g_msgs[6][NB][HIDC][PIX];

__constant__ int c_inc_cnt[6] = {1,3,2,1,2,1};
__constant__ int c_inc_u [6][3] = {{1,0,0},{0,2,4},{1,3,0},{2,0,0},{1,5,0},{4,0,0}};
__constant__ int c_inc_ch[6][3] = {{1,0,0},{1,1,1},{2,1,0},{2,0,0},{3,1,0},{2,0,0}};
__constant__ int c_nch[6]   = {2,4,3,2,3,2};
__constant__ int c_attoff[6]= {1253376,1290240,1363968,1419264,1456128,1511424};

__device__ __forceinline__ float coordf(int ch, int y, int x){
    const float inv = 1.0f/47.0f;
    switch(ch){
        case 0: return x*inv*2.0f-1.0f;
        case 1: return y*inv*2.0f-1.0f;
        case 2: return (x+1)*inv*2.0f-1.0f;
        case 3: return (y+1)*inv*2.0f-1.0f;
        case 4: return (2*x+1)*inv-1.0f;
        case 5: return (2*y+1)*inv-1.0f;
        default: return inv;
    }
}

__device__ __forceinline__ void cpa16(uint32_t dst, const void* src){
    asm volatile("cp.async.ca.shared.global [%0], [%1], 16;" :: "r"(dst), "l"(src));
}

// ---- packed f32x2 helpers (Blackwell sm_100+) ----
__device__ __forceinline__ uint64_t pk2(float lo, float hi){
    uint64_t r; asm("mov.b64 %0, {%1,%2};" : "=l"(r) : "f"(lo), "f"(hi)); return r;
}
__device__ __forceinline__ void upk2(uint64_t v, float& lo, float& hi){
    asm("mov.b64 {%0,%1}, %2;" : "=f"(lo), "=f"(hi) : "l"(v));
}
__device__ __forceinline__ uint64_t ffma2(uint64_t a, uint64_t b, uint64_t c){
    uint64_t d; asm("fma.rn.f32x2 %0, %1, %2, %3;" : "=l"(d) : "l"(a), "l"(b), "l"(c)); return d;
}
__device__ __forceinline__ uint64_t fmul2(uint64_t a, uint64_t b){
    uint64_t d; asm("mul.rn.f32x2 %0, %1, %2;" : "=l"(d) : "l"(a), "l"(b)); return d;
}
__device__ __forceinline__ uint64_t fadd2(uint64_t a, uint64_t b){
    uint64_t d; asm("add.rn.f32x2 %0, %1, %2;" : "=l"(d) : "l"(a), "l"(b)); return d;
}

// ---------------- K1: avgpool 3x3 stride 2 (xp and p_nodes) ----------------
__global__ void k_pool(const float* __restrict__ xp, const float* __restrict__ p_nodes){
    int idx = blockIdx.x*blockDim.x + threadIdx.x;
    const int T1 = NB*256*SP;
    const int T2 = 6*NB*HIDC*SP;
    if (idx < T1){
        int s=idx%SP; int c=(idx/SP)%256; int n=idx/(SP*256);
        int oy=s/HP, ox=s%HP;
        const float* src = xp + ((size_t)(n*256+c)*HH + 2*oy)*HH + 2*ox;
        float sum=0.f;
        #pragma unroll
        for(int dy=0;dy<3;dy++)
            #pragma unroll
            for(int dx=0;dx<3;dx++) sum += src[dy*HH+dx];
        g_ppool[n][c][s]=sum*(1.f/9.f);
    } else if (idx < T1+T2){
        int j=idx-T1;
        int s=j%SP; int c=(j/SP)%HIDC; int n=(j/(SP*HIDC))%NB; int i=j/(SP*HIDC*NB);
        int oy=s/HP, ox=s%HP;
        const float* src = p_nodes + ((size_t)((i*NB+n)*HIDC+c)*HH + 2*oy)*HH + 2*ox;
        float sum=0.f;
        #pragma unroll
        for(int dy=0;dy<3;dy++)
            #pragma unroll
            for(int dx=0;dx<3;dx++) sum += src[dy*HH+dx];
        g_hupool[i][n][c][s]=sum*(1.f/9.f);
    }
}

// ---------------- K2: q projection, transposed (padded) output -------------
__global__ void k_q(const float* __restrict__ Wq){
    int idx = blockIdx.x*blockDim.x + threadIdx.x;
    if (idx >= 6*NB*18*SPAD) return;
    int t=idx%SPAD; int o=(idx/SPAD)%18; int n=(idx/(SPAD*18))%NB; int i=idx/(SPAD*18*NB);
    if (t>=SP){ g_qT[i][n][o][t]=0.f; return; }
    const float* w = Wq + (i*18+o)*18;
    float acc=0.f;
    #pragma unroll
    for(int c=0;c<10;c++) acc += w[c]*g_hupool[i][n][c][t];
    int y=t/HP, x=t%HP;
    #pragma unroll
    for(int cc=0;cc<8;cc++) acc += w[10+cc]*coordf(cc,y,x);
    g_qT[i][n][o][t]=acc;
}

// ---------------- K3: fused k / v / vp, 32-col tile, 256 threads -----------
#define KV_CC 32
#define KV_NCHUNK 70    // 70*32 = 2240 = SPAD (covers pad region, zero-filled)
__global__ __launch_bounds__(256) void k_kv(
        const float* __restrict__ Wk, const float* __restrict__ Wv,
        const float* __restrict__ gv, const float* __restrict__ bv,
        const float* __restrict__ Wp){
    __shared__ float xs [256*32];   // [c][col], 32 KB
    __shared__ float vsm[128*32];   // [r][col], 16 KB
    int blk=blockIdx.x;
    int chunk=blk%KV_NCHUNK; int in_=blk/KV_NCHUNK; int n=in_%NB; int i=in_/NB;
    int s0=chunk*KV_CC;
    int tid=threadIdx.x;
    for(int idx=tid; idx<256*32; idx+=256){
        int c=idx>>5, col=idx&31; int s=s0+col;
        xs[idx] = (s<SP)? g_ppool[n][c][s] : 0.f;
    }
    __syncthreads();

    int rg=tid>>3, cg=tid&7;      // rg 0..31 (4 rows each), cg 0..7 (4 cols each)
    int r0=rg*4, c0=cg*4;
    // ---- stage 1: v = relu(bn(Wv@x)), 4x4 register tile ----
    {
        const float* Wvi = Wv + i*128*256;
        float a[4][4];
        #pragma unroll
        for(int j=0;j<4;j++)
            #pragma unroll
            for(int l=0;l<4;l++) a[j][l]=0.f;
        for(int c=0;c<256;c+=4){
            float wv[4][4], xv[4][4];
            #pragma unroll
            for(int j=0;j<4;j++)
                *(float4*)wv[j] = *(const float4*)&Wvi[(r0+j)*256+c];
            #pragma unroll
            for(int cc=0;cc<4;cc++)
                *(float4*)xv[cc] = *(const float4*)&xs[(c+cc)*32+c0];
            #pragma unroll
            for(int cc=0;cc<4;cc++)
                #pragma unroll
                for(int j=0;j<4;j++)
                    #pragma unroll
                    for(int l=0;l<4;l++)
                        a[j][l] += wv[j][cc]*xv[cc][l];
        }
        #pragma unroll
        for(int j=0;j<4;j++){
            int r=r0+j;
            float g=gv[i*128+r], b=bv[i*128+r];
            float4 o4;
            o4.x=fmaxf(a[j][0]*g+b,0.f);
            o4.y=fmaxf(a[j][1]*g+b,0.f);
            o4.z=fmaxf(a[j][2]*g+b,0.f);
            o4.w=fmaxf(a[j][3]*g+b,0.f);
            *(float4*)&vsm[r*32+c0]=o4;
        }
    }
    // ---- stage 2: k projection (18 rows x 32 cols) ----
    {
        const float* Wki = Wk + i*18*264;
        for(int t=tid; t<18*32; t+=256){
            int o=t>>5, col=t&31;
            int s=s0+col;
            if (s>=SP){ g_k[i][n][o][s]=0.f; continue; }
            float acc=0.f;
            const float* w=Wki+o*264;
            for(int c=0;c<256;c+=4){
                float4 w4=*(const float4*)&w[c];
                acc += w4.x*xs[(c+0)*32+col] + w4.y*xs[(c+1)*32+col]
                     + w4.z*xs[(c+2)*32+col] + w4.w*xs[(c+3)*32+col];
            }
            int sy=s/HP, sx=s%HP;
            #pragma unroll
            for(int cc=0;cc<8;cc++) acc += w[256+cc]*coordf(cc,sy,sx);
            g_k[i][n][o][s]=acc;
        }
    }
    __syncthreads();
    // ---- stage 3: vp = Wp @ vsm (10 rows x 32 cols) ----
    {
        const float* Wpi = Wp + i*10*128;
        for(int t=tid; t<10*32; t+=256){
            int o=t>>5, col=t&31;
            int s=s0+col;
            if (s>=SP){ g_vp[i][n][o][s]=0.f; continue; }
            float acc=0.f;
            const float* w=Wpi+o*128;
            for(int r=0;r<128;r+=4){
                float4 w4=*(const float4*)&w[r];
                acc += w4.x*vsm[(r+0)*32+col] + w4.y*vsm[(r+1)*32+col]
                     + w4.z*vsm[(r+2)*32+col] + w4.w*vsm[(r+3)*32+col];
            }
            g_vp[i][n][o][s]=acc;
        }
    }
}

// ---------------- K4: attention, key-split x7 (5 chunks each), cp.async ----
// grid: (35 q-tiles of 64, KSPLIT, 12), 128 threads
__global__ __launch_bounds__(128,5) void k_att(){
    __shared__ float qs [18*68];       // [c][q] pad 68
    __shared__ __align__(16) float ks [3][18*64];
    __shared__ __align__(16) float vps[3][10*64];
    int tt=blockIdx.x;
    int half=blockIdx.y;
    int in_=blockIdx.z; int n=in_%NB; int i=in_/NB;
    int t0=tt*64;
    int tid=threadIdx.x;
    int qg=tid>>3, kg=tid&7;

    uint32_t ksA[3], vpA[3];
    #pragma unroll
    for(int b=0;b<3;b++){
        ksA[b]=(uint32_t)__cvta_generic_to_shared(&ks[b][0]);
        vpA[b]=(uint32_t)__cvta_generic_to_shared(&vps[b][0]);
    }

    for(int idx=tid; idx<18*64; idx+=128){
        int c=idx>>6, r=idx&63;
        qs[c*68+r] = g_qT[i][n][c][t0+r];
    }
    float acc[4][11];
    #pragma unroll
    for(int j=0;j<4;j++)
        #pragma unroll
        for(int o=0;o<11;o++) acc[j][o]=0.f;

    int cA = half*5;
    int cB = min(35, cA+5);

    // prefetch chunks cA, cA+1
    #pragma unroll
    for(int pf=0; pf<2; pf++){
        if (cA+pf<cB){
            int s0=(cA+pf)*64;
            for(int j=tid; j<448; j+=128){
                if (j<288){ int o=j>>4, q2=j&15;
                    cpa16(ksA[pf]+(uint32_t)(o*64+q2*4)*4u, &g_k[i][n][o][s0+q2*4]);
                } else { int jj=j-288; int o=jj>>4, q2=jj&15;
                    cpa16(vpA[pf]+(uint32_t)(o*64+q2*4)*4u, &g_vp[i][n][o][s0+q2*4]);
                }
            }
            asm volatile("cp.async.commit_group;");
        }
    }

    for(int chunk=cA;chunk<cB;chunk++){
        int b=(chunk-cA)%3;
        if (chunk+1<cB) asm volatile("cp.async.wait_group 1;");
        else            asm volatile("cp.async.wait_group 0;");
        __syncthreads();   // also orders: compute(chunk-1) done before prefetch below
        if (chunk+2<cB){
            int nb=(chunk-cA+2)%3;
            int s0n=(chunk+2)*64;
            for(int j=tid; j<448; j+=128){
                if (j<288){ int o=j>>4, q2=j&15;
                    cpa16(ksA[nb]+(uint32_t)(o*64+q2*4)*4u, &g_k[i][n][o][s0n+q2*4]);
                } else { int jj=j-288; int o=jj>>4, q2=jj&15;
                    cpa16(vpA[nb]+(uint32_t)(o*64+q2*4)*4u, &g_vp[i][n][o][s0n+q2*4]);
                }
            }
            asm volatile("cp.async.commit_group;");
        }

        const float* ksb=&ks[b][0];
        const float* vpb=&vps[b][0];
        int s0=chunk*64;

        // ---- logits: e2[j][p] = packed pair (keys 2p, 2p+1) ----
        uint64_t e2[4][4];
        #pragma unroll
        for(int j=0;j<4;j++)
            #pragma unroll
            for(int p=0;p<4;p++) e2[j][p]=0ull;
        #pragma unroll 6
        for(int c=0;c<18;c++){
            float qv[4];
            *(float4*)qv = *(const float4*)&qs[c*68+qg*4];
            ulonglong2 k01 = *(const ulonglong2*)&ksb[c*64+kg*8];
            ulonglong2 k23 = *(const ulonglong2*)&ksb[c*64+kg*8+4];
            #pragma unroll
            for(int j=0;j<4;j++){
                uint64_t q2v = pk2(qv[j], qv[j]);
                e2[j][0] = ffma2(q2v, k01.x, e2[j][0]);
                e2[j][1] = ffma2(q2v, k01.y, e2[j][1]);
                e2[j][2] = ffma2(q2v, k23.x, e2[j][2]);
                e2[j][3] = ffma2(q2v, k23.y, e2[j][3]);
            }
        }
        // ---- exp ----
        if (s0+64 <= SP){
            #pragma unroll
            for(int j=0;j<4;j++)
                #pragma unroll
                for(int p=0;p<4;p++){
                    float lo,hi; upk2(e2[j][p],lo,hi);
                    e2[j][p]=pk2(__expf(lo),__expf(hi));
                }
        } else {
            int sb=s0+kg*8;
            #pragma unroll
            for(int j=0;j<4;j++)
                #pragma unroll
                for(int p=0;p<4;p++){
                    float lo,hi; upk2(e2[j][p],lo,hi);
                    lo = (sb+2*p  )<SP ? __expf(lo) : 0.f;
                    hi = (sb+2*p+1)<SP ? __expf(hi) : 0.f;
                    e2[j][p]=pk2(lo,hi);
                }
        }
        // ---- accumulate ----
        #pragma unroll
        for(int o=0;o<10;o++){
            ulonglong2 v01 = *(const ulonglong2*)&vpb[o*64+kg*8];
            ulonglong2 v23 = *(const ulonglong2*)&vpb[o*64+kg*8+4];
            #pragma unroll
            for(int j=0;j<4;j++){
                uint64_t t = fmul2(e2[j][3], v23.y);
                t = ffma2(e2[j][2], v23.x, t);
                t = ffma2(e2[j][1], v01.y, t);
                t = ffma2(e2[j][0], v01.x, t);
                float lo,hi; upk2(t,lo,hi);
                acc[j][o] += lo+hi;
            }
        }
        #pragma unroll
        for(int j=0;j<4;j++){
            uint64_t t = fadd2(fadd2(e2[j][0],e2[j][1]), fadd2(e2[j][2],e2[j][3]));
            float lo,hi; upk2(t,lo,hi);
            acc[j][10] += lo+hi;
        }
    }
    // reduce across the 8 key-lanes
    #pragma unroll
    for(int j=0;j<4;j++)
        #pragma unroll
        for(int o=0;o<11;o++){
            float v=acc[j][o];
            v += __shfl_xor_sync(0xffffffffu, v, 4, 8);
            v += __shfl_xor_sync(0xffffffffu, v, 2, 8);
            v += __shfl_xor_sync(0xffffffffu, v, 1, 8);
            acc[j][o]=v;
        }
    if (kg==0){
        #pragma unroll
        for(int j=0;j<4;j++){
            int t=t0+qg*4+j;
            if (t<SP){
                #pragma unroll
                for(int o=0;o<11;o++)
                    g_part[half][i][n][o][t]=acc[j][o];
            }
        }
    }
}

// ---------------- K4b: merge key-split partials, normalize, bn, relu ------
__global__ void k_att_fin(const float* __restrict__ gp, const float* __restrict__ bp){
    int idx=blockIdx.x*blockDim.x+threadIdx.x;
    if (idx >= 6*NB*SP) return;
    int t=idx%SP; int n=(idx/SP)%NB; int i=idx/(SP*NB);
    float a[11];
    #pragma unroll
    for(int o=0;o<11;o++){
        float v=0.f;
        #pragma unroll
        for(int h=0;h<KSPLIT;h++) v += g_part[h][i][n][o][t];
        a[o]=v;
    }
    float inv=1.f/a[10];
    #pragma unroll
    for(int o=0;o<10;o++){
        float val = a[o]*inv*gp[i*10+o]+bp[i*10+o];
        g_ctxp[i][n][o][t]=fmaxf(val,0.f);
    }
}

// ---------------- K5: bilinear upsample + att_list + softmax ---------------
__global__ void k_ups(const float* __restrict__ W_att, const float* __restrict__ b_att,
                      float* __restrict__ out){
    int idx=blockIdx.x*blockDim.x+threadIdx.x;
    if (idx >= 6*NB*PIX) return;
    int p=idx%PIX; int n=(idx/PIX)%NB; int i=idx/(PIX*NB);
    int y=p/HH, x=p%HH;
    const float sc=46.f/95.f;
    float sy=y*sc, sx=x*sc;
    int y0=(int)sy, x0=(int)sx;
    float fy=sy-(float)y0, fx=sx-(float)x0;
    int y1=min(y0+1,HP-1), x1=min(x0+1,HP-1);
    float w00=(1.f-fy)*(1.f-fx), w01=(1.f-fy)*fx, w10=fy*(1.f-fx), w11=fy*fx;
    int p00=y0*HP+x0, p01=y0*HP+x1, p10=y1*HP+x0, p11=y1*HP+x1;
    float f[10];
    #pragma unroll
    for(int c=0;c<10;c++){
        const float* cp=g_ctxp[i][n][c];
        float v=w00*cp[p00]+w01*cp[p01]+w10*cp[p10]+w11*cp[p11];
        f[c]=v; g_Fdep[i][n][c][p]=v;
    }
    int nch=c_nch[i];
    float a[4]; float m=-1e30f;
    for(int ch=0; ch<nch; ch++){
        const float* w=W_att+(i*4+ch)*10;
        float acc=b_att[i*4+ch];
        #pragma unroll
        for(int c=0;c<10;c++) acc += w[c]*f[c];
        a[ch]=acc; m=fmaxf(m,acc);
        out[c_attoff[i] + (n*nch+ch)*PIX + p]=acc;
    }
    float se=0.f;
    for(int ch=0; ch<nch; ch++){ a[ch]=__expf(a[ch]-m); se+=a[ch]; }
    float inv=1.f/se;
    for(int ch=0; ch<nch; ch++) g_attsm[i][n][ch][p]=a[ch]*inv;
}

// ---------------- K6: decomp maps + channel softmax ----------------
__global__ void k_maps(const float* __restrict__ h_nodes,
                       const float* __restrict__ W_du, const float* __restrict__ b_du,
                       const float* __restrict__ W_dl, const float* __restrict__ b_dl,
                       float* __restrict__ out){
    int idx=blockIdx.x*blockDim.x+threadIdx.x;
    if (idx >= NB*PIX) return;
    int p=idx%PIX; int n=idx/PIX;
    float hv[10];
    const float* h0 = h_nodes + (size_t)(0*NB+n)*HIDC*PIX;
    #pragma unroll
    for(int c=0;c<10;c++) hv[c]=h0[c*PIX+p];
    {
        float a[5]; float m=-1e30f;
        for(int k=0;k<5;k++){
            float acc=b_du[k];
            #pragma unroll
            for(int c=0;c<10;c++) acc += W_du[k*10+c]*hv[c];
            a[k]=acc; m=fmaxf(m,acc);
            out[1105920 + (n*5+k)*PIX + p]=acc;
        }
        float se=0.f;
        for(int k=0;k<5;k++){ a[k]=__expf(a[k]-m); se+=a[k]; }
        float inv=1.f/se;
        for(int k=0;k<5;k++) g_dattu[n][k][p]=a[k]*inv;
    }
    const float* h1 = h_nodes + (size_t)(1*NB+n)*HIDC*PIX;
    #pragma unroll
    for(int c=0;c<10;c++) hv[c]=h1[c*PIX+p];
    {
        float a[3]; float m=-1e30f;
        for(int k=0;k<3;k++){
            float acc=b_dl[k];
            #pragma unroll
            for(int c=0;c<10;c++) acc += W_dl[k*10+c]*hv[c];
            a[k]=acc; m=fmaxf(m,acc);
            out[1198080 + (n*3+k)*PIX + p]=acc;
        }
        float se=0.f;
        for(int k=0;k<3;k++){ a[k]=__expf(a[k]-m); se+=a[k]; }
        float inv=1.f/se;
        for(int k=0;k<3;k++) g_dattl[n][k][p]=a[k]*inv;
    }
}

// 3x3 conv, 20 in-ch (10 gated feat + 10 plain), all 10 out-ch per thread
__device__ __forceinline__ void conv20(const float* __restrict__ feat, const float* __restrict__ gate,
                                       const float* __restrict__ pn, const float* __restrict__ W,
                                       int y, int x, float* acc){
    #pragma unroll
    for(int o=0;o<10;o++) acc[o]=0.f;
    #pragma unroll
    for(int ky=0;ky<3;ky++){
        int yy=y+ky-1; if (yy<0||yy>=HH) continue;
        #pragma unroll
        for(int kx=0;kx<3;kx++){
            int xx=x+kx-1; if (xx<0||xx>=HH) continue;
            int pp=yy*HH+xx; int tap=ky*3+kx;
            float gval=gate[pp];
            for(int c=0;c<10;c++){
                float a=feat[c*PIX+pp]*gval;
                float b=pn[c*PIX+pp];
                const float* wr = W + c*9 + tap;
                #pragma unroll
                for(int o=0;o<10;o++)
                    acc[o] += wr[o*180]*a + wr[o*180+90]*b;
            }
        }
    }
}

// ---------------- K7: messages = decomp conv + sum of incoming dep convs ----
__global__ void k_msgs(const float* __restrict__ h_nodes, const float* __restrict__ p_nodes,
                       const float* __restrict__ W_decomp, const float* __restrict__ gdec,
                       const float* __restrict__ bdec,
                       const float* __restrict__ W_dep, const float* __restrict__ gdep,
                       const float* __restrict__ bdep){
    __shared__ float wdec[1800], wdep[1800];
    int tid=threadIdx.x;
    for(int j=tid;j<1800;j+=256){ wdec[j]=W_decomp[j]; wdep[j]=W_dep[j]; }
    __syncthreads();
    int idx=blockIdx.x*256+tid;
    if (idx >= 6*NB*PIX) return;
    int p=idx%PIX; int n=(idx/PIX)%NB; int v=idx/(PIX*NB);
    int y=p/HH, x=p%HH;
    const float* pn = p_nodes + (size_t)(v*NB+n)*HIDC*PIX;
    float acc[10], msg[10];
    {
        int hsel = (v<4)?0:1;
        const float* feat = h_nodes + (size_t)(hsel*NB+n)*HIDC*PIX;
        const float* gate = (v<4)? &g_dattu[n][v+1][0] : &g_dattl[n][v-3][0];
        conv20(feat, gate, pn, wdec, y, x, acc);
        #pragma unroll
        for(int o=0;o<10;o++) msg[o]=fmaxf(gdec[o]*acc[o]+bdec[o], 0.f);
    }
    int cnt=c_inc_cnt[v];
    for(int e=0;e<cnt;e++){
        int u=c_inc_u[v][e], ch=c_inc_ch[v][e];
        conv20(&g_Fdep[u][n][0][0], &g_attsm[u][n][ch][0], pn, wdep, y, x, acc);
        #pragma unroll
        for(int o=0;o<10;o++) msg[o]+=fmaxf(gdep[o]*acc[o]+bdep[o], 0.f);
    }
    #pragma unroll
    for(int o=0;o<10;o++) g_msgs[v][n][o][p]=msg[o];
}

// ---------------- K8: ConvGRU (1x1) ----------------
__global__ void k_gru(const float* __restrict__ p_nodes,
                      const float* __restrict__ Wg, const float* __restrict__ bg,
                      const float* __restrict__ Wc, const float* __restrict__ bc,
                      float* __restrict__ out){
    __shared__ float swg[400], swc[200], sbg[20], sbc[10];
    int tid=threadIdx.x;
    int idx=blockIdx.x*256+tid;
    int p=idx%PIX; int n=(idx/PIX)%NB; int v=idx/(PIX*NB);
    for(int j=tid;j<400;j+=256) swg[j]=Wg[v*400+j];
    for(int j=tid;j<200;j+=256) swc[j]=Wc[v*200+j];
    if (tid<20) sbg[tid]=bg[v*20+tid];
    if (tid<10) sbc[tid]=bc[v*10+tid];
    __syncthreads();
    float m[10], h[10];
    #pragma unroll
    for(int c=0;c<10;c++){
        m[c]=g_msgs[v][n][c][p];
        h[c]=p_nodes[((size_t)(v*NB+n)*HIDC+c)*PIX+p];
    }
    float r[10], u[10];
    #pragma unroll
    for(int j=0;j<10;j++){
        float a=sbg[j];
        #pragma unroll
        for(int c=0;c<10;c++) a += swg[j*20+c]*m[c] + swg[j*20+10+c]*h[c];
        r[j]=1.f/(1.f+__expf(-a));
    }
    #pragma unroll
    for(int j=0;j<10;j++){
        float a=sbg[10+j];
        #pragma unroll
        for(int c=0;c<10;c++) a += swg[(10+j)*20+c]*m[c] + swg[(10+j)*20+10+c]*h[c];
        u[j]=1.f/(1.f+__expf(-a));
    }
    #pragma unroll
    for(int j=0;j<10;j++){
        float a=sbc[j];
        #pragma unroll
        for(int c=0;c<10;c++) a += swc[j*20+c]*m[c] + swc[j*20+10+c]*(r[c]*h[c]);
        float cand=tanhf(a);
        float o=(1.f-u[j])*h[j]+u[j]*cand;
        out[((size_t)(v*NB+n)*HIDC+j)*PIX+p]=o;
    }
}

// ---------------- host ----------------
extern "C" void kernel_launch(void* const* d_in, const int* in_sizes, int n_in,
                              void* d_out, int out_size){
    (void)in_sizes; (void)n_in; (void)out_size;
    const float* h_nodes  =(const float*)d_in[1];
    const float* p_nodes  =(const float*)d_in[2];
    const float* xp       =(const float*)d_in[3];
    const float* Wq       =(const float*)d_in[4];
    const float* Wk       =(const float*)d_in[5];
    const float* Wv       =(const float*)d_in[6];
    const float* gv       =(const float*)d_in[7];
    const float* bv       =(const float*)d_in[8];
    const float* Wp       =(const float*)d_in[9];
    const float* gp       =(const float*)d_in[10];
    const float* bp       =(const float*)d_in[11];
    const float* W_att    =(const float*)d_in[12];
    const float* b_att    =(const float*)d_in[13];
    const float* W_du     =(const float*)d_in[14];
    const float* b_du     =(const float*)d_in[15];
    const float* W_dl     =(const float*)d_in[16];
    const float* b_dl     =(const float*)d_in[17];
    const float* W_decomp =(const float*)d_in[18];
    const float* gdec     =(const float*)d_in[19];
    const float* bdec     =(const float*)d_in[20];
    const float* W_dep    =(const float*)d_in[21];
    const float* gdep     =(const float*)d_in[22];
    const float* bdep     =(const float*)d_in[23];
    const float* Wg       =(const float*)d_in[24];
    const float* bg       =(const float*)d_in[25];
    const float* Wc       =(const float*)d_in[26];
    const float* bc       =(const float*)d_in[27];
    float* out=(float*)d_out;

    {
        int total = NB*256*SP + 6*NB*HIDC*SP;
        k_pool<<<(total+255)/256, 256>>>(xp, p_nodes);
    }
    {
        int total = 6*NB*18*SPAD;
        k_q<<<(total+255)/256, 256>>>(Wq);
    }
    k_kv<<<6*NB*KV_NCHUNK, 256>>>(Wk, Wv, gv, bv, Wp);
    {
        dim3 grid(35, KSPLIT, 6*NB);
        k_att<<<grid, 128>>>();
    }
    k_att_fin<<<(6*NB*SP+255)/256, 256>>>(gp, bp);
    k_ups<<<(6*NB*PIX)/256, 256>>>(W_att, b_att, out);
    k_maps<<<(NB*PIX+255)/256, 256>>>(h_nodes, W_du, b_du, W_dl, b_dl, out);
    k_msgs<<<(6*NB*PIX)/256, 256>>>(h_nodes, p_nodes, W_decomp, gdec, bdec,
                                    W_dep, gdep, bdep);
    k_gru<<<(6*NB*PIX)/256, 256>>>(p_nodes, Wg, bg, Wc, bc, out);
}

// round 16
// speedup vs baseline: 1.1396x; 1.0166x over previous
#include <cuda_runtime.h>
#include <stdint.h>
#include <math.h>

#define NB 2
#define HIDC 10
#define HH 96
#define PIX (96*96)      // 9216
#define HP 47
#define SP (HP*HP)       // 2209
#define SPAD 2240        // padded spatial stride (64-multiple, 16B-aligned rows)
#define KSPLIT 7

// ---------------- scratch (device globals; no allocations) ----------------
__device__ float g_ppool[NB][256][SP];
__device__ float g_hupool[6][NB][HIDC][SP];
__device__ __align__(16) float g_qT[6][NB][18][SPAD];
__device__ __align__(16) float g_k[6][NB][18][SPAD];
__device__ __align__(16) float g_vp[6][NB][HIDC][SPAD];
__device__ float g_part[KSPLIT][6][NB][11][SP];
__device__ float g_ctxp[6][NB][HIDC][SP];
__device__ float g_Fdep[6][NB][HIDC][PIX];
__device__ float g_attsm[6][NB][4][PIX];
__device__ float g_dattu[NB][5][PIX];
__device__ float g_dattl[NB][3][PIX];
__device__ float g_msgs[6][NB][HIDC][PIX];

__constant__ int c_inc_cnt[6] = {1,3,2,1,2,1};
__constant__ int c_inc_u [6][3] = {{1,0,0},{0,2,4},{1,3,0},{2,0,0},{1,5,0},{4,0,0}};
__constant__ int c_inc_ch[6][3] = {{1,0,0},{1,1,1},{2,1,0},{2,0,0},{3,1,0},{2,0,0}};
__constant__ int c_nch[6]   = {2,4,3,2,3,2};
__constant__ int c_attoff[6]= {1253376,1290240,1363968,1419264,1456128,1511424};

__device__ __forceinline__ float coordf(int ch, int y, int x){
    const float inv = 1.0f/47.0f;
    switch(ch){
        case 0: return x*inv*2.0f-1.0f;
        case 1: return y*inv*2.0f-1.0f;
        case 2: return (x+1)*inv*2.0f-1.0f;
        case 3: return (y+1)*inv*2.0f-1.0f;
        case 4: return (2*x+1)*inv-1.0f;
        case 5: return (2*y+1)*inv-1.0f;
        default: return inv;
    }
}

__device__ __forceinline__ void cpa16(uint32_t dst, const void* src){
    asm volatile("cp.async.ca.shared.global [%0], [%1], 16;" :: "r"(dst), "l"(src));
}

// ---- packed f32x2 helpers (Blackwell sm_100+) ----
__device__ __forceinline__ uint64_t pk2(float lo, float hi){
    uint64_t r; asm("mov.b64 %0, {%1,%2};" : "=l"(r) : "f"(lo), "f"(hi)); return r;
}
__device__ __forceinline__ void upk2(uint64_t v, float& lo, float& hi){
    asm("mov.b64 {%0,%1}, %2;" : "=f"(lo), "=f"(hi) : "l"(v));
}
__device__ __forceinline__ uint64_t ffma2(uint64_t a, uint64_t b, uint64_t c){
    uint64_t d; asm("fma.rn.f32x2 %0, %1, %2, %3;" : "=l"(d) : "l"(a), "l"(b), "l"(c)); return d;
}
__device__ __forceinline__ uint64_t fmul2(uint64_t a, uint64_t b){
    uint64_t d; asm("mul.rn.f32x2 %0, %1, %2;" : "=l"(d) : "l"(a), "l"(b)); return d;
}
__device__ __forceinline__ uint64_t fadd2(uint64_t a, uint64_t b){
    uint64_t d; asm("add.rn.f32x2 %0, %1, %2;" : "=l"(d) : "l"(a), "l"(b)); return d;
}

// ---------------- K1a: avgpool of xp -> ppool ----------------
__global__ void k_pool_x(const float* __restrict__ xp){
    int idx = blockIdx.x*blockDim.x + threadIdx.x;
    if (idx >= NB*256*SP) return;
    int s=idx%SP; int c=(idx/SP)%256; int n=idx/(SP*256);
    int oy=s/HP, ox=s%HP;
    const float* src = xp + ((size_t)(n*256+c)*HH + 2*oy)*HH + 2*ox;
    float sum=0.f;
    #pragma unroll
    for(int dy=0;dy<3;dy++)
        #pragma unroll
        for(int dx=0;dx<3;dx++) sum += src[dy*HH+dx];
    g_ppool[n][c][s]=sum*(1.f/9.f);
}

// ---------------- K1b: avgpool of p_nodes -> hupool ----------------
__global__ void k_pool_h(const float* __restrict__ p_nodes){
    int idx = blockIdx.x*blockDim.x + threadIdx.x;
    if (idx >= 6*NB*HIDC*SP) return;
    int s=idx%SP; int c=(idx/SP)%HIDC; int n=(idx/(SP*HIDC))%NB; int i=idx/(SP*HIDC*NB);
    int oy=s/HP, ox=s%HP;
    const float* src = p_nodes + ((size_t)((i*NB+n)*HIDC+c)*HH + 2*oy)*HH + 2*ox;
    float sum=0.f;
    #pragma unroll
    for(int dy=0;dy<3;dy++)
        #pragma unroll
        for(int dx=0;dx<3;dx++) sum += src[dy*HH+dx];
    g_hupool[i][n][c][s]=sum*(1.f/9.f);
}

// ---------------- K2: q projection, transposed (padded) output -------------
__global__ void k_q(const float* __restrict__ Wq){
    int idx = blockIdx.x*blockDim.x + threadIdx.x;
    if (idx >= 6*NB*18*SPAD) return;
    int t=idx%SPAD; int o=(idx/SPAD)%18; int n=(idx/(SPAD*18))%NB; int i=idx/(SPAD*18*NB);
    if (t>=SP){ g_qT[i][n][o][t]=0.f; return; }
    const float* w = Wq + (i*18+o)*18;
    float acc=0.f;
    #pragma unroll
    for(int c=0;c<10;c++) acc += w[c]*g_hupool[i][n][c][t];
    int y=t/HP, x=t%HP;
    #pragma unroll
    for(int cc=0;cc<8;cc++) acc += w[10+cc]*coordf(cc,y,x);
    g_qT[i][n][o][t]=acc;
}

// ---------------- K3: fused k / v / vp, 32-col tile, 256 threads -----------
#define KV_CC 32
#define KV_NCHUNK 70    // 70*32 = 2240 = SPAD (covers pad region, zero-filled)
__global__ __launch_bounds__(256) void k_kv(
        const float* __restrict__ Wk, const float* __restrict__ Wv,
        const float* __restrict__ gv, const float* __restrict__ bv,
        const float* __restrict__ Wp){
    __shared__ float xs [256*32];   // [c][col], 32 KB
    __shared__ float vsm[128*32];   // [r][col], 16 KB
    int blk=blockIdx.x;
    int chunk=blk%KV_NCHUNK; int in_=blk/KV_NCHUNK; int n=in_%NB; int i=in_/NB;
    int s0=chunk*KV_CC;
    int tid=threadIdx.x;
    for(int idx=tid; idx<256*32; idx+=256){
        int c=idx>>5, col=idx&31; int s=s0+col;
        xs[idx] = (s<SP)? g_ppool[n][c][s] : 0.f;
    }
    __syncthreads();

    int rg=tid>>3, cg=tid&7;
    int r0=rg*4, c0=cg*4;
    {
        const float* Wvi = Wv + i*128*256;
        float a[4][4];
        #pragma unroll
        for(int j=0;j<4;j++)
            #pragma unroll
            for(int l=0;l<4;l++) a[j][l]=0.f;
        for(int c=0;c<256;c+=4){
            float wv[4][4], xv[4][4];
            #pragma unroll
            for(int j=0;j<4;j++)
                *(float4*)wv[j] = *(const float4*)&Wvi[(r0+j)*256+c];
            #pragma unroll
            for(int cc=0;cc<4;cc++)
                *(float4*)xv[cc] = *(const float4*)&xs[(c+cc)*32+c0];
            #pragma unroll
            for(int cc=0;cc<4;cc++)
                #pragma unroll
                for(int j=0;j<4;j++)
                    #pragma unroll
                    for(int l=0;l<4;l++)
                        a[j][l] += wv[j][cc]*xv[cc][l];
        }
        #pragma unroll
        for(int j=0;j<4;j++){
            int r=r0+j;
            float g=gv[i*128+r], b=bv[i*128+r];
            float4 o4;
            o4.x=fmaxf(a[j][0]*g+b,0.f);
            o4.y=fmaxf(a[j][1]*g+b,0.f);
            o4.z=fmaxf(a[j][2]*g+b,0.f);
            o4.w=fmaxf(a[j][3]*g+b,0.f);
            *(float4*)&vsm[r*32+c0]=o4;
        }
    }
    {
        const float* Wki = Wk + i*18*264;
        for(int t=tid; t<18*32; t+=256){
            int o=t>>5, col=t&31;
            int s=s0+col;
            if (s>=SP){ g_k[i][n][o][s]=0.f; continue; }
            float acc=0.f;
            const float* w=Wki+o*264;
            for(int c=0;c<256;c+=4){
                float4 w4=*(const float4*)&w[c];
                acc += w4.x*xs[(c+0)*32+col] + w4.y*xs[(c+1)*32+col]
                     + w4.z*xs[(c+2)*32+col] + w4.w*xs[(c+3)*32+col];
            }
            int sy=s/HP, sx=s%HP;
            #pragma unroll
            for(int cc=0;cc<8;cc++) acc += w[256+cc]*coordf(cc,sy,sx);
            g_k[i][n][o][s]=acc;
        }
    }
    __syncthreads();
    {
        const float* Wpi = Wp + i*10*128;
        for(int t=tid; t<10*32; t+=256){
            int o=t>>5, col=t&31;
            int s=s0+col;
            if (s>=SP){ g_vp[i][n][o][s]=0.f; continue; }
            float acc=0.f;
            const float* w=Wpi+o*128;
            for(int r=0;r<128;r+=4){
                float4 w4=*(const float4*)&w[r];
                acc += w4.x*vsm[(r+0)*32+col] + w4.y*vsm[(r+1)*32+col]
                     + w4.z*vsm[(r+2)*32+col] + w4.w*vsm[(r+3)*32+col];
            }
            g_vp[i][n][o][s]=acc;
        }
    }
}

// ---------------- K4: attention, key-split x7 (5 chunks each), cp.async ----
// grid: (35 q-tiles of 64, KSPLIT, 12), 128 threads
__global__ __launch_bounds__(128,5) void k_att(){
    __shared__ float qs [18*68];       // [c][q] pad 68
    __shared__ __align__(16) float ks [3][18*64];
    __shared__ __align__(16) float vps[3][10*64];
    int tt=blockIdx.x;
    int half=blockIdx.y;
    int in_=blockIdx.z; int n=in_%NB; int i=in_/NB;
    int t0=tt*64;
    int tid=threadIdx.x;
    int qg=tid>>3, kg=tid&7;

    uint32_t ksA[3], vpA[3];
    #pragma unroll
    for(int b=0;b<3;b++){
        ksA[b]=(uint32_t)__cvta_generic_to_shared(&ks[b][0]);
        vpA[b]=(uint32_t)__cvta_generic_to_shared(&vps[b][0]);
    }

    for(int idx=tid; idx<18*64; idx+=128){
        int c=idx>>6, r=idx&63;
        qs[c*68+r] = g_qT[i][n][c][t0+r];
    }
    float acc[4][11];
    #pragma unroll
    for(int j=0;j<4;j++)
        #pragma unroll
        for(int o=0;o<11;o++) acc[j][o]=0.f;

    int cA = half*5;
    int cB = min(35, cA+5);

    // prefetch chunks cA, cA+1
    #pragma unroll
    for(int pf=0; pf<2; pf++){
        if (cA+pf<cB){
            int s0=(cA+pf)*64;
            for(int j=tid; j<448; j+=128){
                if (j<288){ int o=j>>4, q2=j&15;
                    cpa16(ksA[pf]+(uint32_t)(o*64+q2*4)*4u, &g_k[i][n][o][s0+q2*4]);
                } else { int jj=j-288; int o=jj>>4, q2=jj&15;
                    cpa16(vpA[pf]+(uint32_t)(o*64+q2*4)*4u, &g_vp[i][n][o][s0+q2*4]);
                }
            }
            asm volatile("cp.async.commit_group;");
        }
    }

    for(int chunk=cA;chunk<cB;chunk++){
        int b=(chunk-cA)%3;
        if (chunk+1<cB) asm volatile("cp.async.wait_group 1;");
        else            asm volatile("cp.async.wait_group 0;");
        __syncthreads();
        if (chunk+2<cB){
            int nb=(chunk-cA+2)%3;
            int s0n=(chunk+2)*64;
            for(int j=tid; j<448; j+=128){
                if (j<288){ int o=j>>4, q2=j&15;
                    cpa16(ksA[nb]+(uint32_t)(o*64+q2*4)*4u, &g_k[i][n][o][s0n+q2*4]);
                } else { int jj=j-288; int o=jj>>4, q2=jj&15;
                    cpa16(vpA[nb]+(uint32_t)(o*64+q2*4)*4u, &g_vp[i][n][o][s0n+q2*4]);
                }
            }
            asm volatile("cp.async.commit_group;");
        }

        const float* ksb=&ks[b][0];
        const float* vpb=&vps[b][0];
        int s0=chunk*64;

        uint64_t e2[4][4];
        #pragma unroll
        for(int j=0;j<4;j++)
            #pragma unroll
            for(int p=0;p<4;p++) e2[j][p]=0ull;
        #pragma unroll 6
        for(int c=0;c<18;c++){
            float qv[4];
            *(float4*)qv = *(const float4*)&qs[c*68+qg*4];
            ulonglong2 k01 = *(const ulonglong2*)&ksb[c*64+kg*8];
            ulonglong2 k23 = *(const ulonglong2*)&ksb[c*64+kg*8+4];
            #pragma unroll
            for(int j=0;j<4;j++){
                uint64_t q2v = pk2(qv[j], qv[j]);
                e2[j][0] = ffma2(q2v, k01.x, e2[j][0]);
                e2[j][1] = ffma2(q2v, k01.y, e2[j][1]);
                e2[j][2] = ffma2(q2v, k23.x, e2[j][2]);
                e2[j][3] = ffma2(q2v, k23.y, e2[j][3]);
            }
        }
        if (s0+64 <= SP){
            #pragma unroll
            for(int j=0;j<4;j++)
                #pragma unroll
                for(int p=0;p<4;p++){
                    float lo,hi; upk2(e2[j][p],lo,hi);
                    e2[j][p]=pk2(__expf(lo),__expf(hi));
                }
        } else {
            int sb=s0+kg*8;
            #pragma unroll
            for(int j=0;j<4;j++)
                #pragma unroll
                for(int p=0;p<4;p++){
                    float lo,hi; upk2(e2[j][p],lo,hi);
                    lo = (sb+2*p  )<SP ? __expf(lo) : 0.f;
                    hi = (sb+2*p+1)<SP ? __expf(hi) : 0.f;
                    e2[j][p]=pk2(lo,hi);
                }
        }
        #pragma unroll
        for(int o=0;o<10;o++){
            ulonglong2 v01 = *(const ulonglong2*)&vpb[o*64+kg*8];
            ulonglong2 v23 = *(const ulonglong2*)&vpb[o*64+kg*8+4];
            #pragma unroll
            for(int j=0;j<4;j++){
                uint64_t t = fmul2(e2[j][3], v23.y);
                t = ffma2(e2[j][2], v23.x, t);
                t = ffma2(e2[j][1], v01.y, t);
                t = ffma2(e2[j][0], v01.x, t);
                float lo,hi; upk2(t,lo,hi);
                acc[j][o] += lo+hi;
            }
        }
        #pragma unroll
        for(int j=0;j<4;j++){
            uint64_t t = fadd2(fadd2(e2[j][0],e2[j][1]), fadd2(e2[j][2],e2[j][3]));
            float lo,hi; upk2(t,lo,hi);
            acc[j][10] += lo+hi;
        }
    }
    #pragma unroll
    for(int j=0;j<4;j++)
        #pragma unroll
        for(int o=0;o<11;o++){
            float v=acc[j][o];
            v += __shfl_xor_sync(0xffffffffu, v, 4, 8);
            v += __shfl_xor_sync(0xffffffffu, v, 2, 8);
            v += __shfl_xor_sync(0xffffffffu, v, 1, 8);
            acc[j][o]=v;
        }
    if (kg==0){
        #pragma unroll
        for(int j=0;j<4;j++){
            int t=t0+qg*4+j;
            if (t<SP){
                #pragma unroll
                for(int o=0;o<11;o++)
                    g_part[half][i][n][o][t]=acc[j][o];
            }
        }
    }
}

// ---------------- K4b: merge key-split partials, normalize, bn, relu ------
__global__ void k_att_fin(const float* __restrict__ gp, const float* __restrict__ bp){
    int idx=blockIdx.x*blockDim.x+threadIdx.x;
    if (idx >= 6*NB*SP) return;
    int t=idx%SP; int n=(idx/SP)%NB; int i=idx/(SP*NB);
    float a[11];
    #pragma unroll
    for(int o=0;o<11;o++){
        float v=0.f;
        #pragma unroll
        for(int h=0;h<KSPLIT;h++) v += g_part[h][i][n][o][t];
        a[o]=v;
    }
    float inv=1.f/a[10];
    #pragma unroll
    for(int o=0;o<10;o++){
        float val = a[o]*inv*gp[i*10+o]+bp[i*10+o];
        g_ctxp[i][n][o][t]=fmaxf(val,0.f);
    }
}

// ---------------- K5: bilinear upsample + att_list + softmax ---------------
__global__ void k_ups(const float* __restrict__ W_att, const float* __restrict__ b_att,
                      float* __restrict__ out){
    int idx=blockIdx.x*blockDim.x+threadIdx.x;
    if (idx >= 6*NB*PIX) return;
    int p=idx%PIX; int n=(idx/PIX)%NB; int i=idx/(PIX*NB);
    int y=p/HH, x=p%HH;
    const float sc=46.f/95.f;
    float sy=y*sc, sx=x*sc;
    int y0=(int)sy, x0=(int)sx;
    float fy=sy-(float)y0, fx=sx-(float)x0;
    int y1=min(y0+1,HP-1), x1=min(x0+1,HP-1);
    float w00=(1.f-fy)*(1.f-fx), w01=(1.f-fy)*fx, w10=fy*(1.f-fx), w11=fy*fx;
    int p00=y0*HP+x0, p01=y0*HP+x1, p10=y1*HP+x0, p11=y1*HP+x1;
    float f[10];
    #pragma unroll
    for(int c=0;c<10;c++){
        const float* cp=g_ctxp[i][n][c];
        float v=w00*cp[p00]+w01*cp[p01]+w10*cp[p10]+w11*cp[p11];
        f[c]=v; g_Fdep[i][n][c][p]=v;
    }
    int nch=c_nch[i];
    float a[4]; float m=-1e30f;
    for(int ch=0; ch<nch; ch++){
        const float* w=W_att+(i*4+ch)*10;
        float acc=b_att[i*4+ch];
        #pragma unroll
        for(int c=0;c<10;c++) acc += w[c]*f[c];
        a[ch]=acc; m=fmaxf(m,acc);
        out[c_attoff[i] + (n*nch+ch)*PIX + p]=acc;
    }
    float se=0.f;
    for(int ch=0; ch<nch; ch++){ a[ch]=__expf(a[ch]-m); se+=a[ch]; }
    float inv=1.f/se;
    for(int ch=0; ch<nch; ch++) g_attsm[i][n][ch][p]=a[ch]*inv;
}

// ---------------- K6: decomp maps + channel softmax ----------------
__global__ void k_maps(const float* __restrict__ h_nodes,
                       const float* __restrict__ W_du, const float* __restrict__ b_du,
                       const float* __restrict__ W_dl, const float* __restrict__ b_dl,
                       float* __restrict__ out){
    int idx=blockIdx.x*blockDim.x+threadIdx.x;
    if (idx >= NB*PIX) return;
    int p=idx%PIX; int n=idx/PIX;
    float hv[10];
    const float* h0 = h_nodes + (size_t)(0*NB+n)*HIDC*PIX;
    #pragma unroll
    for(int c=0;c<10;c++) hv[c]=h0[c*PIX+p];
    {
        float a[5]; float m=-1e30f;
        for(int k=0;k<5;k++){
            float acc=b_du[k];
            #pragma unroll
            for(int c=0;c<10;c++) acc += W_du[k*10+c]*hv[c];
            a[k]=acc; m=fmaxf(m,acc);
            out[1105920 + (n*5+k)*PIX + p]=acc;
        }
        float se=0.f;
        for(int k=0;k<5;k++){ a[k]=__expf(a[k]-m); se+=a[k]; }
        float inv=1.f/se;
        for(int k=0;k<5;k++) g_dattu[n][k][p]=a[k]*inv;
    }
    const float* h1 = h_nodes + (size_t)(1*NB+n)*HIDC*PIX;
    #pragma unroll
    for(int c=0;c<10;c++) hv[c]=h1[c*PIX+p];
    {
        float a[3]; float m=-1e30f;
        for(int k=0;k<3;k++){
            float acc=b_dl[k];
            #pragma unroll
            for(int c=0;c<10;c++) acc += W_dl[k*10+c]*hv[c];
            a[k]=acc; m=fmaxf(m,acc);
            out[1198080 + (n*3+k)*PIX + p]=acc;
        }
        float se=0.f;
        for(int k=0;k<3;k++){ a[k]=__expf(a[k]-m); se+=a[k]; }
        float inv=1.f/se;
        for(int k=0;k<3;k++) g_dattl[n][k][p]=a[k]*inv;
    }
}

// 3x3 conv, 20 in-ch (10 gated feat + 10 plain), all 10 out-ch per thread
__device__ __forceinline__ void conv20(const float* __restrict__ feat, const float* __restrict__ gate,
                                       const float* __restrict__ pn, const float* __restrict__ W,
                                       int y, int x, float* acc){
    #pragma unroll
    for(int o=0;o<10;o++) acc[o]=0.f;
    #pragma unroll
    for(int ky=0;ky<3;ky++){
        int yy=y+ky-1; if (yy<0||yy>=HH) continue;
        #pragma unroll
        for(int kx=0;kx<3;kx++){
            int xx=x+kx-1; if (xx<0||xx>=HH) continue;
            int pp=yy*HH+xx; int tap=ky*3+kx;
            float gval=gate[pp];
            for(int c=0;c<10;c++){
                float a=feat[c*PIX+pp]*gval;
                float b=pn[c*PIX+pp];
                const float* wr = W + c*9 + tap;
                #pragma unroll
                for(int o=0;o<10;o++)
                    acc[o] += wr[o*180]*a + wr[o*180+90]*b;
            }
        }
    }
}

// ---------------- K7: messages = decomp conv + sum of incoming dep convs ----
__global__ void k_msgs(const float* __restrict__ h_nodes, const float* __restrict__ p_nodes,
                       const float* __restrict__ W_decomp, const float* __restrict__ gdec,
                       const float* __restrict__ bdec,
                       const float* __restrict__ W_dep, const float* __restrict__ gdep,
                       const float* __restrict__ bdep){
    __shared__ float wdec[1800], wdep[1800];
    int tid=threadIdx.x;
    for(int j=tid;j<1800;j+=256){ wdec[j]=W_decomp[j]; wdep[j]=W_dep[j]; }
    __syncthreads();
    int idx=blockIdx.x*256+tid;
    if (idx >= 6*NB*PIX) return;
    int p=idx%PIX; int n=(idx/PIX)%NB; int v=idx/(PIX*NB);
    int y=p/HH, x=p%HH;
    const float* pn = p_nodes + (size_t)(v*NB+n)*HIDC*PIX;
    float acc[10], msg[10];
    {
        int hsel = (v<4)?0:1;
        const float* feat = h_nodes + (size_t)(hsel*NB+n)*HIDC*PIX;
        const float* gate = (v<4)? &g_dattu[n][v+1][0] : &g_dattl[n][v-3][0];
        conv20(feat, gate, pn, wdec, y, x, acc);
        #pragma unroll
        for(int o=0;o<10;o++) msg[o]=fmaxf(gdec[o]*acc[o]+bdec[o], 0.f);
    }
    int cnt=c_inc_cnt[v];
    for(int e=0;e<cnt;e++){
        int u=c_inc_u[v][e], ch=c_inc_ch[v][e];
        conv20(&g_Fdep[u][n][0][0], &g_attsm[u][n][ch][0], pn, wdep, y, x, acc);
        #pragma unroll
        for(int o=0;o<10;o++) msg[o]+=fmaxf(gdep[o]*acc[o]+bdep[o], 0.f);
    }
    #pragma unroll
    for(int o=0;o<10;o++) g_msgs[v][n][o][p]=msg[o];
}

// ---------------- K8: ConvGRU (1x1) ----------------
__global__ void k_gru(const float* __restrict__ p_nodes,
                      const float* __restrict__ Wg, const float* __restrict__ bg,
                      const float* __restrict__ Wc, const float* __restrict__ bc,
                      float* __restrict__ out){
    __shared__ float swg[400], swc[200], sbg[20], sbc[10];
    int tid=threadIdx.x;
    int idx=blockIdx.x*256+tid;
    int p=idx%PIX; int n=(idx/PIX)%NB; int v=idx/(PIX*NB);
    for(int j=tid;j<400;j+=256) swg[j]=Wg[v*400+j];
    for(int j=tid;j<200;j+=256) swc[j]=Wc[v*200+j];
    if (tid<20) sbg[tid]=bg[v*20+tid];
    if (tid<10) sbc[tid]=bc[v*10+tid];
    __syncthreads();
    float m[10], h[10];
    #pragma unroll
    for(int c=0;c<10;c++){
        m[c]=g_msgs[v][n][c][p];
        h[c]=p_nodes[((size_t)(v*NB+n)*HIDC+c)*PIX+p];
    }
    float r[10], u[10];
    #pragma unroll
    for(int j=0;j<10;j++){
        float a=sbg[j];
        #pragma unroll
        for(int c=0;c<10;c++) a += swg[j*20+c]*m[c] + swg[j*20+10+c]*h[c];
        r[j]=1.f/(1.f+__expf(-a));
    }
    #pragma unroll
    for(int j=0;j<10;j++){
        float a=sbg[10+j];
        #pragma unroll
        for(int c=0;c<10;c++) a += swg[(10+j)*20+c]*m[c] + swg[(10+j)*20+10+c]*h[c];
        u[j]=1.f/(1.f+__expf(-a));
    }
    #pragma unroll
    for(int j=0;j<10;j++){
        float a=sbc[j];
        #pragma unroll
        for(int c=0;c<10;c++) a += swc[j*20+c]*m[c] + swc[j*20+10+c]*(r[c]*h[c]);
        float cand=tanhf(a);
        float o=(1.f-u[j])*h[j]+u[j]*cand;
        out[((size_t)(v*NB+n)*HIDC+j)*PIX+p]=o;
    }
}

// ---------------- host ----------------
extern "C" void kernel_launch(void* const* d_in, const int* in_sizes, int n_in,
                              void* d_out, int out_size){
    (void)in_sizes; (void)n_in; (void)out_size;
    const float* h_nodes  =(const float*)d_in[1];
    const float* p_nodes  =(const float*)d_in[2];
    const float* xp       =(const float*)d_in[3];
    const float* Wq       =(const float*)d_in[4];
    const float* Wk       =(const float*)d_in[5];
    const float* Wv       =(const float*)d_in[6];
    const float* gv       =(const float*)d_in[7];
    const float* bv       =(const float*)d_in[8];
    const float* Wp       =(const float*)d_in[9];
    const float* gp       =(const float*)d_in[10];
    const float* bp       =(const float*)d_in[11];
    const float* W_att    =(const float*)d_in[12];
    const float* b_att    =(const float*)d_in[13];
    const float* W_du     =(const float*)d_in[14];
    const float* b_du     =(const float*)d_in[15];
    const float* W_dl     =(const float*)d_in[16];
    const float* b_dl     =(const float*)d_in[17];
    const float* W_decomp =(const float*)d_in[18];
    const float* gdec     =(const float*)d_in[19];
    const float* bdec     =(const float*)d_in[20];
    const float* W_dep    =(const float*)d_in[21];
    const float* gdep     =(const float*)d_in[22];
    const float* bdep     =(const float*)d_in[23];
    const float* Wg       =(const float*)d_in[24];
    const float* bg       =(const float*)d_in[25];
    const float* Wc       =(const float*)d_in[26];
    const float* bc       =(const float*)d_in[27];
    float* out=(float*)d_out;

    cudaStream_t s2;
    cudaStreamCreateWithFlags(&s2, cudaStreamNonBlocking);
    cudaEvent_t eFork, eQ, eMaps;
    cudaEventCreateWithFlags(&eFork, cudaEventDisableTiming);
    cudaEventCreateWithFlags(&eQ,    cudaEventDisableTiming);
    cudaEventCreateWithFlags(&eMaps, cudaEventDisableTiming);

    // fork side stream off the capture stream
    cudaEventRecord(eFork, 0);
    cudaStreamWaitEvent(s2, eFork, 0);

    // side stream: hupool -> q, then decomp maps (independent of attention chain)
    k_pool_h<<<(6*NB*HIDC*SP+255)/256, 256, 0, s2>>>(p_nodes);
    k_q<<<(6*NB*18*SPAD+255)/256, 256, 0, s2>>>(Wq);
    cudaEventRecord(eQ, s2);
    k_maps<<<(NB*PIX+255)/256, 256, 0, s2>>>(h_nodes, W_du, b_du, W_dl, b_dl, out);
    cudaEventRecord(eMaps, s2);

    // main stream: ppool -> kv
    k_pool_x<<<(NB*256*SP+255)/256, 256>>>(xp);
    k_kv<<<6*NB*KV_NCHUNK, 256>>>(Wk, Wv, gv, bv, Wp);
    // join q before attention
    cudaStreamWaitEvent(0, eQ, 0);
    {
        dim3 grid(35, KSPLIT, 6*NB);
        k_att<<<grid, 128>>>();
    }
    k_att_fin<<<(6*NB*SP+255)/256, 256>>>(gp, bp);
    k_ups<<<(6*NB*PIX)/256, 256>>>(W_att, b_att, out);
    // join maps before messages
    cudaStreamWaitEvent(0, eMaps, 0);
    k_msgs<<<(6*NB*PIX)/256, 256>>>(h_nodes, p_nodes, W_decomp, gdec, bdec,
                                    W_dep, gdep, bdep);
    k_gru<<<(6*NB*PIX)/256, 256>>>(p_nodes, Wg, bg, Wc, bc, out);
}